// round 1
// baseline (speedup 1.0000x reference)
#include <cuda_runtime.h>
#include <math.h>

#define N_USERS 50000
#define N_ENT   100000
#define N_INT   5
#define EMB     128
#define N_REL   20
#define N_EDGES 1000000
#define NNZ     1000000

// ---------------- scratch (device globals; no runtime allocation) ----------------
__device__ __align__(16) float g_e_cur[(size_t)N_ENT * EMB];
__device__ __align__(16) float g_u_cur[(size_t)N_USERS * EMB];
__device__ __align__(16) float g_e_agg[(size_t)N_ENT * EMB];
__device__ __align__(16) float g_u_agg[(size_t)N_USERS * EMB];
__device__ float g_deg[N_ENT];
__device__ __align__(16) float g_intent2[N_INT * EMB];

// ---------------- helpers ----------------
__device__ __forceinline__ float warp_sum(float v) {
    #pragma unroll
    for (int o = 16; o; o >>= 1) v += __shfl_xor_sync(0xffffffffu, v, o);
    return v;
}

__device__ __forceinline__ void red_v4(float* dst, float4 m) {
    asm volatile("red.global.add.v4.f32 [%0], {%1,%2,%3,%4};"
                 :: "l"(dst), "f"(m.x), "f"(m.y), "f"(m.z), "f"(m.w) : "memory");
}

// ---------------- init / zero ----------------
__global__ void zero_agg_kernel() {
    size_t total = (size_t)(N_ENT + N_USERS) * (EMB / 4);
    size_t i = (size_t)blockIdx.x * blockDim.x + threadIdx.x;
    if (i >= total) return;
    float4 z = make_float4(0.f, 0.f, 0.f, 0.f);
    size_t ne = (size_t)N_ENT * (EMB / 4);
    if (i < ne) ((float4*)g_e_agg)[i] = z;
    else        ((float4*)g_u_agg)[i - ne] = z;
}

__global__ void zero_deg_kernel() {
    int i = blockIdx.x * blockDim.x + threadIdx.x;
    if (i < N_ENT) g_deg[i] = 0.f;
}

__global__ void count_kernel(const int* __restrict__ edge_index) {
    int e = blockIdx.x * blockDim.x + threadIdx.x;
    if (e >= N_EDGES) return;
    atomicAdd(&g_deg[edge_index[e]], 1.0f);
}

// ---------------- intent2 (hop-invariant) ----------------
__global__ void intent2_kernel(const float* __restrict__ intent_emb,
                               const float* __restrict__ r_emb) {
    __shared__ float r[N_REL][EMB];
    __shared__ float att[N_REL];
    int tid = threadIdx.x;  // 128 threads
    for (int i = tid; i < N_REL * EMB; i += blockDim.x)
        r[i / EMB][i % EMB] = r_emb[i];
    __syncthreads();

    const int starts[5] = {0, 0, 4, 8, 12};
    const int counts[5] = {20, 4, 4, 4, 8};

    for (int i = 0; i < N_INT; i++) {
        int s = starts[i], n = counts[i];
        if (tid < n) {
            float d = 0.f;
            #pragma unroll 4
            for (int k = 0; k < EMB; k++)
                d += intent_emb[i * EMB + k] * r[s + tid][k];
            att[tid] = d;
        }
        __syncthreads();
        if (tid == 0) {
            float mx = -1e30f;
            for (int q = 0; q < n; q++) mx = fmaxf(mx, att[q]);
            float se = 0.f;
            for (int q = 0; q < n; q++) { att[q] = expf(att[q] - mx); se += att[q]; }
            float inv = 1.f / se;
            for (int q = 0; q < n; q++) att[q] *= inv;
        }
        __syncthreads();
        // all_intent[k] = mean(att_r * r[k]); intent2 = (all_intent + intent_emb)/2
        {
            float acc = 0.f;
            for (int q = 0; q < n; q++) acc += att[q] * r[s + q][tid];
            acc /= (float)n;
            g_intent2[i * EMB + tid] = 0.5f * (acc + intent_emb[i * EMB + tid]);
        }
        __syncthreads();
    }
}

// ---------------- distance-correlation (cor), one block ----------------
__device__ float block_sum_128(float v, float* sh) {
    v = warp_sum(v);
    int w = threadIdx.x >> 5;
    if ((threadIdx.x & 31) == 0) sh[w] = v;
    __syncthreads();
    float r = sh[0] + sh[1] + sh[2] + sh[3];
    __syncthreads();
    return r;
}

__global__ void cor_kernel(const float* __restrict__ intent_emb,
                           float* __restrict__ out_cor) {
    __shared__ float t[N_INT][EMB];
    __shared__ float am_a[EMB], am_b[EMB];
    __shared__ float redbuf[4];
    int tid = threadIdx.x;  // 128
    for (int i = tid; i < N_INT * EMB; i += blockDim.x)
        t[i / EMB][i % EMB] = intent_emb[i];
    __syncthreads();

    float cor = 0.f;
    for (int i = 0; i < N_INT; i++) {
        for (int j = i + 1; j < N_INT; j++) {
            float tik = t[i][tid], tjk = t[j][tid];
            // row means of symmetric distance matrices
            float sa = 0.f, sb = 0.f;
            for (int l = 0; l < EMB; l++) {
                float da = tik - t[i][l];
                float db = tjk - t[j][l];
                sa += sqrtf(fmaxf(da * da, 0.f) + 1e-8f);
                sb += sqrtf(fmaxf(db * db, 0.f) + 1e-8f);
            }
            am_a[tid] = sa * (1.f / EMB);
            am_b[tid] = sb * (1.f / EMB);
            __syncthreads();
            float ga = 0.f, gb = 0.f;
            for (int l = 0; l < EMB; l++) { ga += am_a[l]; gb += am_b[l]; }
            ga *= (1.f / EMB); gb *= (1.f / EMB);

            float amk = am_a[tid], bmk = am_b[tid];
            float pab = 0.f, paa = 0.f, pbb = 0.f;
            for (int l = 0; l < EMB; l++) {
                float da = tik - t[i][l];
                float db = tjk - t[j][l];
                float A = sqrtf(fmaxf(da * da, 0.f) + 1e-8f) - amk - am_a[l] + ga;
                float B = sqrtf(fmaxf(db * db, 0.f) + 1e-8f) - bmk - am_b[l] + gb;
                pab += A * B; paa += A * A; pbb += B * B;
            }
            float SAB = block_sum_128(pab, redbuf);
            float SAA = block_sum_128(paa, redbuf);
            float SBB = block_sum_128(pbb, redbuf);
            const float d2 = (float)EMB * (float)EMB;
            float dAB = sqrtf(fmaxf(SAB / d2, 0.f) + 1e-8f);
            float dAA = sqrtf(fmaxf(SAA / d2, 0.f) + 1e-8f);
            float dBB = sqrtf(fmaxf(SBB / d2, 0.f) + 1e-8f);
            cor += dAB / sqrtf(dAA * dBB + 1e-8f);
            __syncthreads();
        }
    }
    if (tid == 0) *out_cor = cor;
}

// ---------------- scatters (warp per edge, v4 reductions) ----------------
__global__ void scatter_edges(const int* __restrict__ edge_index,
                              const int* __restrict__ edge_type,
                              const float* __restrict__ r_emb) {
    unsigned gid = blockIdx.x * blockDim.x + threadIdx.x;
    unsigned e = gid >> 5, lane = gid & 31;
    if (e >= N_EDGES) return;
    int head = edge_index[e];
    int tail = edge_index[N_EDGES + e];
    int rel  = edge_type[e] - 1;
    float4 ev = ((const float4*)(g_e_cur + (size_t)tail * EMB))[lane];
    float4 rv = ((const float4*)(r_emb + (size_t)rel * EMB))[lane];
    float4 m = make_float4(ev.x * rv.x, ev.y * rv.y, ev.z * rv.z, ev.w * rv.w);
    red_v4(g_e_agg + (size_t)head * EMB + lane * 4, m);
}

__global__ void scatter_interact(const int* __restrict__ rows,
                                 const int* __restrict__ cols,
                                 const float* __restrict__ vals) {
    unsigned gid = blockIdx.x * blockDim.x + threadIdx.x;
    unsigned e = gid >> 5, lane = gid & 31;
    if (e >= NNZ) return;
    int r = rows[e], c = cols[e];
    float v = vals[e];
    float4 ev = ((const float4*)(g_e_cur + (size_t)c * EMB))[lane];
    float4 m = make_float4(ev.x * v, ev.y * v, ev.z * v, ev.w * v);
    red_v4(g_u_agg + (size_t)r * EMB + lane * 4, m);
}

// ---------------- finalize kernels (warp per row) ----------------
__global__ void finalize_e(float* __restrict__ res_e) {
    unsigned gid = blockIdx.x * blockDim.x + threadIdx.x;
    unsigned row = gid >> 5, lane = gid & 31;
    if (row >= N_ENT) return;
    float c = g_deg[row];
    float4 s = ((const float4*)(g_e_agg + (size_t)row * EMB))[lane];
    float inv = (c > 0.f) ? (1.f / fmaxf(c, 1.f)) : 0.f;
    float4 v = make_float4(s.x * inv, s.y * inv, s.z * inv, s.w * inv);
    float ss = warp_sum(v.x * v.x + v.y * v.y + v.z * v.z + v.w * v.w);
    float in2 = 1.f / fmaxf(sqrtf(ss), 1e-12f);
    float4 vn = make_float4(v.x * in2, v.y * in2, v.z * in2, v.w * in2);
    ((float4*)(g_e_cur + (size_t)row * EMB))[lane] = vn;
    float4* rp = (float4*)(res_e + (size_t)row * EMB) + lane;
    float4 r = *rp;
    *rp = make_float4(r.x + vn.x, r.y + vn.y, r.z + vn.z, r.w + vn.w);
}

__global__ void finalize_u(float* __restrict__ res_u) {
    unsigned gid = blockIdx.x * blockDim.x + threadIdx.x;
    unsigned row = gid >> 5, lane = gid & 31;
    if (row >= N_USERS) return;
    float4 uv = ((const float4*)(g_u_cur + (size_t)row * EMB))[lane];
    float4 t2[N_INT];
    float dots[N_INT];
    #pragma unroll
    for (int i = 0; i < N_INT; i++) {
        t2[i] = ((const float4*)(g_intent2 + i * EMB))[lane];
        float p = uv.x * t2[i].x + uv.y * t2[i].y + uv.z * t2[i].z + uv.w * t2[i].w;
        dots[i] = warp_sum(p);
    }
    float mx = dots[0];
    #pragma unroll
    for (int i = 1; i < N_INT; i++) mx = fmaxf(mx, dots[i]);
    float se = 0.f;
    #pragma unroll
    for (int i = 0; i < N_INT; i++) { dots[i] = expf(dots[i] - mx); se += dots[i]; }
    float inv = 1.f / se;
    float4 w = make_float4(0.f, 0.f, 0.f, 0.f);
    #pragma unroll
    for (int i = 0; i < N_INT; i++) {
        float sc = dots[i] * inv;
        w.x += sc * t2[i].x; w.y += sc * t2[i].y; w.z += sc * t2[i].z; w.w += sc * t2[i].w;
    }
    float4 a = ((const float4*)(g_u_agg + (size_t)row * EMB))[lane];
    // u_agg * (score @ intent2) + u_agg = a * (1 + w)
    float4 o = make_float4(a.x * (1.f + w.x), a.y * (1.f + w.y),
                           a.z * (1.f + w.z), a.w * (1.f + w.w));
    float ss = warp_sum(o.x * o.x + o.y * o.y + o.z * o.z + o.w * o.w);
    float in2 = 1.f / fmaxf(sqrtf(ss), 1e-12f);
    float4 on = make_float4(o.x * in2, o.y * in2, o.z * in2, o.w * in2);
    ((float4*)(g_u_cur + (size_t)row * EMB))[lane] = on;
    float4* rp = (float4*)(res_u + (size_t)row * EMB) + lane;
    float4 r = *rp;
    *rp = make_float4(r.x + on.x, r.y + on.y, r.z + on.z, r.w + on.w);
}

// ---------------- launch ----------------
extern "C" void kernel_launch(void* const* d_in, const int* in_sizes, int n_in,
                              void* d_out, int out_size) {
    const float* user_emb   = (const float*)d_in[0];
    const float* entity_emb = (const float*)d_in[1];
    const float* intent_emb = (const float*)d_in[2];
    const int*   edge_index = (const int*)d_in[3];
    const int*   edge_type  = (const int*)d_in[4];
    const int*   irows      = (const int*)d_in[5];
    const int*   icols      = (const int*)d_in[6];
    const float* ivals      = (const float*)d_in[7];
    const float* r_emb      = (const float*)d_in[8];

    float* out   = (float*)d_out;
    float* res_e = out;
    float* res_u = out + (size_t)N_ENT * EMB;
    float* cor_o = out + (size_t)N_ENT * EMB + (size_t)N_USERS * EMB;

    const size_t ebytes = sizeof(float) * (size_t)N_ENT * EMB;
    const size_t ubytes = sizeof(float) * (size_t)N_USERS * EMB;

    cudaMemcpyAsync(res_e, entity_emb, ebytes, cudaMemcpyDeviceToDevice);
    cudaMemcpyAsync(res_u, user_emb,   ubytes, cudaMemcpyDeviceToDevice);
    cudaMemcpyToSymbolAsync(g_e_cur, entity_emb, ebytes, 0, cudaMemcpyDeviceToDevice);
    cudaMemcpyToSymbolAsync(g_u_cur, user_emb,   ubytes, 0, cudaMemcpyDeviceToDevice);

    zero_deg_kernel<<<(N_ENT + 255) / 256, 256>>>();
    count_kernel<<<(N_EDGES + 255) / 256, 256>>>(edge_index);
    intent2_kernel<<<1, 128>>>(intent_emb, r_emb);
    cor_kernel<<<1, 128>>>(intent_emb, cor_o);

    const int zero_total = (N_ENT + N_USERS) * (EMB / 4);
    for (int hop = 0; hop < 2; hop++) {
        zero_agg_kernel<<<(zero_total + 255) / 256, 256>>>();
        scatter_edges<<<(int)(((size_t)N_EDGES * 32 + 255) / 256), 256>>>(edge_index, edge_type, r_emb);
        scatter_interact<<<(int)(((size_t)NNZ * 32 + 255) / 256), 256>>>(irows, icols, ivals);
        finalize_u<<<(int)(((size_t)N_USERS * 32 + 255) / 256), 256>>>(res_u);  // uses old u_cur
        finalize_e<<<(int)(((size_t)N_ENT * 32 + 255) / 256), 256>>>(res_e);    // updates e_cur for next hop
    }
    (void)in_sizes; (void)n_in; (void)out_size;
}

// round 2
// speedup vs baseline: 1.2954x; 1.2954x over previous
#include <cuda_runtime.h>
#include <math.h>

#define N_USERS 50000
#define N_ENT   100000
#define N_INT   5
#define EMB     128
#define N_REL   20
#define N_EDGES 1000000
#define NNZ     1000000

// ---------------- scratch (device globals; no runtime allocation) ----------------
__device__ __align__(16) float g_e_cur[(size_t)N_ENT * EMB];
__device__ __align__(16) float g_u_cur[(size_t)N_USERS * EMB];
__device__ __align__(16) float g_e_agg[(size_t)N_ENT * EMB];
__device__ __align__(16) float g_u_agg[(size_t)N_USERS * EMB];
__device__ float g_deg[N_ENT];
__device__ __align__(16) float g_intent2[N_INT * EMB];

// ---------------- helpers ----------------
__device__ __forceinline__ float warp_sum(float v) {
    #pragma unroll
    for (int o = 16; o; o >>= 1) v += __shfl_xor_sync(0xffffffffu, v, o);
    return v;
}

__device__ __forceinline__ void red_v4(float* dst, float4 m) {
    asm volatile("red.global.add.v4.f32 [%0], {%1,%2,%3,%4};"
                 :: "l"(dst), "f"(m.x), "f"(m.y), "f"(m.z), "f"(m.w) : "memory");
}

// ---------------- init / zero ----------------
__global__ void zero_agg_kernel() {
    size_t total = (size_t)(N_ENT + N_USERS) * (EMB / 4);
    size_t i = (size_t)blockIdx.x * blockDim.x + threadIdx.x;
    if (i >= total) return;
    float4 z = make_float4(0.f, 0.f, 0.f, 0.f);
    size_t ne = (size_t)N_ENT * (EMB / 4);
    if (i < ne) ((float4*)g_e_agg)[i] = z;
    else        ((float4*)g_u_agg)[i - ne] = z;
}

__global__ void zero_deg_cor_kernel(float* __restrict__ cor_o) {
    int i = blockIdx.x * blockDim.x + threadIdx.x;
    if (i < N_ENT) g_deg[i] = 0.f;
    if (i == 0) *cor_o = 0.f;
}

__global__ void count_kernel(const int* __restrict__ edge_index) {
    int e = blockIdx.x * blockDim.x + threadIdx.x;
    if (e >= N_EDGES) return;
    atomicAdd(&g_deg[edge_index[e]], 1.0f);
}

// ---------------- intent2 (hop-invariant) ----------------
__global__ void intent2_kernel(const float* __restrict__ intent_emb,
                               const float* __restrict__ r_emb) {
    __shared__ float r[N_REL][EMB];
    __shared__ float att[N_REL];
    int tid = threadIdx.x;  // 128 threads
    for (int i = tid; i < N_REL * EMB; i += blockDim.x)
        r[i / EMB][i % EMB] = r_emb[i];
    __syncthreads();

    const int starts[5] = {0, 0, 4, 8, 12};
    const int counts[5] = {20, 4, 4, 4, 8};

    for (int i = 0; i < N_INT; i++) {
        int s = starts[i], n = counts[i];
        if (tid < n) {
            float d = 0.f;
            #pragma unroll 4
            for (int k = 0; k < EMB; k++)
                d += intent_emb[i * EMB + k] * r[s + tid][k];
            att[tid] = d;
        }
        __syncthreads();
        if (tid == 0) {
            float mx = -1e30f;
            for (int q = 0; q < n; q++) mx = fmaxf(mx, att[q]);
            float se = 0.f;
            for (int q = 0; q < n; q++) { att[q] = expf(att[q] - mx); se += att[q]; }
            float inv = 1.f / se;
            for (int q = 0; q < n; q++) att[q] *= inv;
        }
        __syncthreads();
        {
            float acc = 0.f;
            for (int q = 0; q < n; q++) acc += att[q] * r[s + q][tid];
            acc /= (float)n;
            g_intent2[i * EMB + tid] = 0.5f * (acc + intent_emb[i * EMB + tid]);
        }
        __syncthreads();
    }
}

// ---------------- distance-correlation: one block PER PAIR (10 blocks) ----------------
__device__ float block_sum_128(float v, float* sh) {
    v = warp_sum(v);
    int w = threadIdx.x >> 5;
    if ((threadIdx.x & 31) == 0) sh[w] = v;
    __syncthreads();
    float r = sh[0] + sh[1] + sh[2] + sh[3];
    __syncthreads();
    return r;
}

__global__ void cor_pair_kernel(const float* __restrict__ intent_emb,
                                float* __restrict__ out_cor) {
    // map blockIdx.x (0..9) -> pair (i, j), i<j, over N_INT=5
    const int pi[10] = {0,0,0,0,1,1,1,2,2,3};
    const int pj[10] = {1,2,3,4,2,3,4,3,4,4};
    int i = pi[blockIdx.x], j = pj[blockIdx.x];

    __shared__ float ti[EMB], tj[EMB];
    __shared__ float am_a[EMB], am_b[EMB];
    __shared__ float redbuf[4];
    int tid = threadIdx.x;  // 128
    ti[tid] = intent_emb[i * EMB + tid];
    tj[tid] = intent_emb[j * EMB + tid];
    __syncthreads();

    float tik = ti[tid], tjk = tj[tid];
    // row means of symmetric distance matrices
    float sa = 0.f, sb = 0.f;
    #pragma unroll 4
    for (int l = 0; l < EMB; l++) {
        float da = tik - ti[l];
        float db = tjk - tj[l];
        sa += sqrtf(da * da + 1e-8f);
        sb += sqrtf(db * db + 1e-8f);
    }
    am_a[tid] = sa * (1.f / EMB);
    am_b[tid] = sb * (1.f / EMB);
    __syncthreads();
    float ga = 0.f, gb = 0.f;
    #pragma unroll 4
    for (int l = 0; l < EMB; l++) { ga += am_a[l]; gb += am_b[l]; }
    ga *= (1.f / EMB); gb *= (1.f / EMB);

    float amk = am_a[tid], bmk = am_b[tid];
    float pab = 0.f, paa = 0.f, pbb = 0.f;
    #pragma unroll 4
    for (int l = 0; l < EMB; l++) {
        float da = tik - ti[l];
        float db = tjk - tj[l];
        float A = sqrtf(da * da + 1e-8f) - amk - am_a[l] + ga;
        float B = sqrtf(db * db + 1e-8f) - bmk - am_b[l] + gb;
        pab += A * B; paa += A * A; pbb += B * B;
    }
    float SAB = block_sum_128(pab, redbuf);
    float SAA = block_sum_128(paa, redbuf);
    float SBB = block_sum_128(pbb, redbuf);
    if (tid == 0) {
        const float d2 = (float)EMB * (float)EMB;
        float dAB = sqrtf(fmaxf(SAB / d2, 0.f) + 1e-8f);
        float dAA = sqrtf(fmaxf(SAA / d2, 0.f) + 1e-8f);
        float dBB = sqrtf(fmaxf(SBB / d2, 0.f) + 1e-8f);
        atomicAdd(out_cor, dAB / sqrtf(dAA * dBB + 1e-8f));
    }
}

// ---------------- merged scatter (warp per edge/interaction, v4 reductions) ----------------
__global__ void scatter_all(const int* __restrict__ edge_index,
                            const int* __restrict__ edge_type,
                            const float* __restrict__ r_emb,
                            const int* __restrict__ rows,
                            const int* __restrict__ cols,
                            const float* __restrict__ vals) {
    unsigned gid = blockIdx.x * blockDim.x + threadIdx.x;
    unsigned e = gid >> 5, lane = gid & 31;
    if (e < N_EDGES) {
        int head = edge_index[e];
        int tail = edge_index[N_EDGES + e];
        int rel  = edge_type[e] - 1;
        float4 ev = ((const float4*)(g_e_cur + (size_t)tail * EMB))[lane];
        float4 rv = ((const float4*)(r_emb + (size_t)rel * EMB))[lane];
        float4 m = make_float4(ev.x * rv.x, ev.y * rv.y, ev.z * rv.z, ev.w * rv.w);
        red_v4(g_e_agg + (size_t)head * EMB + lane * 4, m);
    } else if (e < N_EDGES + NNZ) {
        unsigned k = e - N_EDGES;
        int r = rows[k], c = cols[k];
        float v = vals[k];
        float4 ev = ((const float4*)(g_e_cur + (size_t)c * EMB))[lane];
        float4 m = make_float4(ev.x * v, ev.y * v, ev.z * v, ev.w * v);
        red_v4(g_u_agg + (size_t)r * EMB + lane * 4, m);
    }
}

// ---------------- merged finalize (warp per row) ----------------
__global__ void finalize_all(float* __restrict__ res_e, float* __restrict__ res_u) {
    unsigned gid = blockIdx.x * blockDim.x + threadIdx.x;
    unsigned row = gid >> 5, lane = gid & 31;
    if (row < N_USERS) {
        // ---- user row ----
        float4 uv = ((const float4*)(g_u_cur + (size_t)row * EMB))[lane];
        float4 t2[N_INT];
        float dots[N_INT];
        #pragma unroll
        for (int i = 0; i < N_INT; i++) {
            t2[i] = ((const float4*)(g_intent2 + i * EMB))[lane];
            float p = uv.x * t2[i].x + uv.y * t2[i].y + uv.z * t2[i].z + uv.w * t2[i].w;
            dots[i] = warp_sum(p);
        }
        float mx = dots[0];
        #pragma unroll
        for (int i = 1; i < N_INT; i++) mx = fmaxf(mx, dots[i]);
        float se = 0.f;
        #pragma unroll
        for (int i = 0; i < N_INT; i++) { dots[i] = expf(dots[i] - mx); se += dots[i]; }
        float inv = 1.f / se;
        float4 w = make_float4(0.f, 0.f, 0.f, 0.f);
        #pragma unroll
        for (int i = 0; i < N_INT; i++) {
            float sc = dots[i] * inv;
            w.x += sc * t2[i].x; w.y += sc * t2[i].y; w.z += sc * t2[i].z; w.w += sc * t2[i].w;
        }
        float4 a = ((const float4*)(g_u_agg + (size_t)row * EMB))[lane];
        float4 o = make_float4(a.x * (1.f + w.x), a.y * (1.f + w.y),
                               a.z * (1.f + w.z), a.w * (1.f + w.w));
        float ss = warp_sum(o.x * o.x + o.y * o.y + o.z * o.z + o.w * o.w);
        float in2 = 1.f / fmaxf(sqrtf(ss), 1e-12f);
        float4 on = make_float4(o.x * in2, o.y * in2, o.z * in2, o.w * in2);
        ((float4*)(g_u_cur + (size_t)row * EMB))[lane] = on;
        float4* rp = (float4*)(res_u + (size_t)row * EMB) + lane;
        float4 r = *rp;
        *rp = make_float4(r.x + on.x, r.y + on.y, r.z + on.z, r.w + on.w);
    } else if (row < N_USERS + N_ENT) {
        // ---- entity row ----
        unsigned er = row - N_USERS;
        float c = g_deg[er];
        float4 s = ((const float4*)(g_e_agg + (size_t)er * EMB))[lane];
        float inv = (c > 0.f) ? (1.f / fmaxf(c, 1.f)) : 0.f;
        float4 v = make_float4(s.x * inv, s.y * inv, s.z * inv, s.w * inv);
        float ss = warp_sum(v.x * v.x + v.y * v.y + v.z * v.z + v.w * v.w);
        float in2 = 1.f / fmaxf(sqrtf(ss), 1e-12f);
        float4 vn = make_float4(v.x * in2, v.y * in2, v.z * in2, v.w * in2);
        ((float4*)(g_e_cur + (size_t)er * EMB))[lane] = vn;
        float4* rp = (float4*)(res_e + (size_t)er * EMB) + lane;
        float4 r = *rp;
        *rp = make_float4(r.x + vn.x, r.y + vn.y, r.z + vn.z, r.w + vn.w);
    }
}

// ---------------- launch ----------------
extern "C" void kernel_launch(void* const* d_in, const int* in_sizes, int n_in,
                              void* d_out, int out_size) {
    const float* user_emb   = (const float*)d_in[0];
    const float* entity_emb = (const float*)d_in[1];
    const float* intent_emb = (const float*)d_in[2];
    const int*   edge_index = (const int*)d_in[3];
    const int*   edge_type  = (const int*)d_in[4];
    const int*   irows      = (const int*)d_in[5];
    const int*   icols      = (const int*)d_in[6];
    const float* ivals      = (const float*)d_in[7];
    const float* r_emb      = (const float*)d_in[8];

    float* out   = (float*)d_out;
    float* res_e = out;
    float* res_u = out + (size_t)N_ENT * EMB;
    float* cor_o = out + (size_t)N_ENT * EMB + (size_t)N_USERS * EMB;

    const size_t ebytes = sizeof(float) * (size_t)N_ENT * EMB;
    const size_t ubytes = sizeof(float) * (size_t)N_USERS * EMB;

    cudaMemcpyAsync(res_e, entity_emb, ebytes, cudaMemcpyDeviceToDevice);
    cudaMemcpyAsync(res_u, user_emb,   ubytes, cudaMemcpyDeviceToDevice);
    cudaMemcpyToSymbolAsync(g_e_cur, entity_emb, ebytes, 0, cudaMemcpyDeviceToDevice);
    cudaMemcpyToSymbolAsync(g_u_cur, user_emb,   ubytes, 0, cudaMemcpyDeviceToDevice);

    zero_deg_cor_kernel<<<(N_ENT + 255) / 256, 256>>>(cor_o);
    count_kernel<<<(N_EDGES + 255) / 256, 256>>>(edge_index);
    intent2_kernel<<<1, 128>>>(intent_emb, r_emb);
    cor_pair_kernel<<<10, 128>>>(intent_emb, cor_o);

    const int zero_total = (N_ENT + N_USERS) * (EMB / 4);
    const int scat_total = N_EDGES + NNZ;
    const int fin_total  = N_USERS + N_ENT;
    for (int hop = 0; hop < 2; hop++) {
        zero_agg_kernel<<<(zero_total + 255) / 256, 256>>>();
        scatter_all<<<(int)(((size_t)scat_total * 32 + 255) / 256), 256>>>(
            edge_index, edge_type, r_emb, irows, icols, ivals);
        finalize_all<<<(int)(((size_t)fin_total * 32 + 255) / 256), 256>>>(res_e, res_u);
    }
    (void)in_sizes; (void)n_in; (void)out_size;
}

// round 3
// speedup vs baseline: 1.6118x; 1.2442x over previous
#include <cuda_runtime.h>
#include <math.h>

#define N_USERS 50000
#define N_ENT   100000
#define N_INT   5
#define EMB     128
#define N_REL   20
#define N_EDGES 1000000
#define NNZ     1000000

// ---------------- scratch (device globals; no runtime allocation) ----------------
__device__ __align__(16) float g_e_buf0[(size_t)N_ENT * EMB];
__device__ __align__(16) float g_e_buf1[(size_t)N_ENT * EMB];
__device__ __align__(16) float g_u_cur[(size_t)N_USERS * EMB];
__device__ __align__(16) float g_intent2[N_INT * EMB];

__device__ int g_ecnt[N_ENT + 1];    // counts -> exclusive offsets (+ total at [N])
__device__ int g_ucnt[N_USERS + 1];
__device__ int g_ecur[N_ENT];        // fill cursors
__device__ int g_ucur[N_USERS];
__device__ int   g_epay[N_EDGES];    // tail*32 + rel
__device__ int   g_icol[NNZ];
__device__ float g_ival[NNZ];

// ---------------- helpers ----------------
__device__ __forceinline__ float warp_sum(float v) {
    #pragma unroll
    for (int o = 16; o; o >>= 1) v += __shfl_xor_sync(0xffffffffu, v, o);
    return v;
}

// ---------------- prologue: counts ----------------
__global__ void zero_counts_kernel(float* __restrict__ cor_o) {
    int i = blockIdx.x * blockDim.x + threadIdx.x;
    if (i <= N_ENT) g_ecnt[i] = 0;
    if (i <= N_USERS) g_ucnt[i] = 0;
    if (i == 0) *cor_o = 0.f;
}

__global__ void count_kernel(const int* __restrict__ edge_index,
                             const int* __restrict__ irows) {
    int i = blockIdx.x * blockDim.x + threadIdx.x;
    if (i < N_EDGES) atomicAdd(&g_ecnt[edge_index[i]], 1);
    else if (i < N_EDGES + NNZ) atomicAdd(&g_ucnt[irows[i - N_EDGES]], 1);
}

// block 0 scans entity counts, block 1 scans user counts (1024 threads each)
__global__ void scan_kernel() {
    __shared__ int part[1024];
    int* cnt   = (blockIdx.x == 0) ? g_ecnt : g_ucnt;
    int* cur   = (blockIdx.x == 0) ? g_ecur : g_ucur;
    int  n     = (blockIdx.x == 0) ? N_ENT  : N_USERS;
    int tid = threadIdx.x;
    int chunk = (n + 1023) / 1024;
    int lo = tid * chunk;
    int hi = lo + chunk; if (hi > n) hi = n; if (lo > n) lo = n;
    int s = 0;
    for (int i = lo; i < hi; i++) s += cnt[i];
    part[tid] = s;
    __syncthreads();
    // Hillis-Steele inclusive scan
    for (int off = 1; off < 1024; off <<= 1) {
        int v = part[tid];
        int add = (tid >= off) ? part[tid - off] : 0;
        __syncthreads();
        part[tid] = v + add;
        __syncthreads();
    }
    int base = (tid > 0) ? part[tid - 1] : 0;
    int run = base;
    for (int i = lo; i < hi; i++) {
        int c = cnt[i];
        cnt[i] = run;
        cur[i] = run;
        run += c;
    }
    if (tid == 1023) cnt[n] = part[1023];
}

__global__ void fill_kernel(const int* __restrict__ edge_index,
                            const int* __restrict__ edge_type,
                            const int* __restrict__ irows,
                            const int* __restrict__ icols,
                            const float* __restrict__ ivals) {
    int i = blockIdx.x * blockDim.x + threadIdx.x;
    if (i < N_EDGES) {
        int head = edge_index[i];
        int tail = edge_index[N_EDGES + i];
        int rel  = edge_type[i] - 1;
        int pos = atomicAdd(&g_ecur[head], 1);
        g_epay[pos] = (tail << 5) | rel;
    } else if (i < N_EDGES + NNZ) {
        int k = i - N_EDGES;
        int r = irows[k];
        int pos = atomicAdd(&g_ucur[r], 1);
        g_icol[pos] = icols[k];
        g_ival[pos] = ivals[k];
    }
}

// ---------------- intent2 (hop-invariant) ----------------
__global__ void intent2_kernel(const float* __restrict__ intent_emb,
                               const float* __restrict__ r_emb) {
    __shared__ float r[N_REL][EMB];
    __shared__ float att[N_REL];
    int tid = threadIdx.x;  // 128 threads
    for (int i = tid; i < N_REL * EMB; i += blockDim.x)
        r[i / EMB][i % EMB] = r_emb[i];
    __syncthreads();

    const int starts[5] = {0, 0, 4, 8, 12};
    const int counts[5] = {20, 4, 4, 4, 8};

    for (int i = 0; i < N_INT; i++) {
        int s = starts[i], n = counts[i];
        if (tid < n) {
            float d = 0.f;
            #pragma unroll 4
            for (int k = 0; k < EMB; k++)
                d += intent_emb[i * EMB + k] * r[s + tid][k];
            att[tid] = d;
        }
        __syncthreads();
        if (tid == 0) {
            float mx = -1e30f;
            for (int q = 0; q < n; q++) mx = fmaxf(mx, att[q]);
            float se = 0.f;
            for (int q = 0; q < n; q++) { att[q] = expf(att[q] - mx); se += att[q]; }
            float inv = 1.f / se;
            for (int q = 0; q < n; q++) att[q] *= inv;
        }
        __syncthreads();
        {
            float acc = 0.f;
            for (int q = 0; q < n; q++) acc += att[q] * r[s + q][tid];
            acc /= (float)n;
            g_intent2[i * EMB + tid] = 0.5f * (acc + intent_emb[i * EMB + tid]);
        }
        __syncthreads();
    }
}

// ---------------- distance-correlation: one block per pair ----------------
__device__ float block_sum_128(float v, float* sh) {
    v = warp_sum(v);
    int w = threadIdx.x >> 5;
    if ((threadIdx.x & 31) == 0) sh[w] = v;
    __syncthreads();
    float r = sh[0] + sh[1] + sh[2] + sh[3];
    __syncthreads();
    return r;
}

__global__ void cor_pair_kernel(const float* __restrict__ intent_emb,
                                float* __restrict__ out_cor) {
    const int pi[10] = {0,0,0,0,1,1,1,2,2,3};
    const int pj[10] = {1,2,3,4,2,3,4,3,4,4};
    int i = pi[blockIdx.x], j = pj[blockIdx.x];

    __shared__ float ti[EMB], tj[EMB];
    __shared__ float am_a[EMB], am_b[EMB];
    __shared__ float redbuf[4];
    int tid = threadIdx.x;  // 128
    ti[tid] = intent_emb[i * EMB + tid];
    tj[tid] = intent_emb[j * EMB + tid];
    __syncthreads();

    float tik = ti[tid], tjk = tj[tid];
    float sa = 0.f, sb = 0.f;
    #pragma unroll 4
    for (int l = 0; l < EMB; l++) {
        float da = tik - ti[l];
        float db = tjk - tj[l];
        sa += sqrtf(da * da + 1e-8f);
        sb += sqrtf(db * db + 1e-8f);
    }
    am_a[tid] = sa * (1.f / EMB);
    am_b[tid] = sb * (1.f / EMB);
    __syncthreads();
    float ga = 0.f, gb = 0.f;
    #pragma unroll 4
    for (int l = 0; l < EMB; l++) { ga += am_a[l]; gb += am_b[l]; }
    ga *= (1.f / EMB); gb *= (1.f / EMB);

    float amk = am_a[tid], bmk = am_b[tid];
    float pab = 0.f, paa = 0.f, pbb = 0.f;
    #pragma unroll 4
    for (int l = 0; l < EMB; l++) {
        float da = tik - ti[l];
        float db = tjk - tj[l];
        float A = sqrtf(da * da + 1e-8f) - amk - am_a[l] + ga;
        float B = sqrtf(db * db + 1e-8f) - bmk - am_b[l] + gb;
        pab += A * B; paa += A * A; pbb += B * B;
    }
    float SAB = block_sum_128(pab, redbuf);
    float SAA = block_sum_128(paa, redbuf);
    float SBB = block_sum_128(pbb, redbuf);
    if (tid == 0) {
        const float d2 = (float)EMB * (float)EMB;
        float dAB = sqrtf(fmaxf(SAB / d2, 0.f) + 1e-8f);
        float dAA = sqrtf(fmaxf(SAA / d2, 0.f) + 1e-8f);
        float dBB = sqrtf(fmaxf(SBB / d2, 0.f) + 1e-8f);
        atomicAdd(out_cor, dAB / sqrtf(dAA * dBB + 1e-8f));
    }
}

// ---------------- fused hop kernel (warp per row, CSR gather, inline finalize) -----
__global__ void hop_kernel(const float* __restrict__ e_src,
                           float* __restrict__ e_dst,
                           const float* __restrict__ r_emb,
                           float* __restrict__ res_e,
                           float* __restrict__ res_u) {
    unsigned gid = blockIdx.x * blockDim.x + threadIdx.x;
    unsigned row = gid >> 5, lane = gid & 31;
    if (row < N_ENT) {
        int beg = g_ecnt[row], end = g_ecnt[row + 1];
        float4 acc = make_float4(0.f, 0.f, 0.f, 0.f);
        for (int k = beg; k < end; k++) {
            int p = g_epay[k];
            int tail = p >> 5, rel = p & 31;
            float4 ev = ((const float4*)(e_src + (size_t)tail * EMB))[lane];
            float4 rv = ((const float4*)(r_emb + (size_t)rel * EMB))[lane];
            acc.x += ev.x * rv.x; acc.y += ev.y * rv.y;
            acc.z += ev.z * rv.z; acc.w += ev.w * rv.w;
        }
        int cnt = end - beg;
        float inv = (cnt > 0) ? (1.f / (float)cnt) : 0.f;
        float4 v = make_float4(acc.x * inv, acc.y * inv, acc.z * inv, acc.w * inv);
        float ss = warp_sum(v.x * v.x + v.y * v.y + v.z * v.z + v.w * v.w);
        float in2 = 1.f / fmaxf(sqrtf(ss), 1e-12f);
        float4 vn = make_float4(v.x * in2, v.y * in2, v.z * in2, v.w * in2);
        ((float4*)(e_dst + (size_t)row * EMB))[lane] = vn;
        float4* rp = (float4*)(res_e + (size_t)row * EMB) + lane;
        float4 r = *rp;
        *rp = make_float4(r.x + vn.x, r.y + vn.y, r.z + vn.z, r.w + vn.w);
    } else if (row < N_ENT + N_USERS) {
        unsigned ur = row - N_ENT;
        // score from OLD u_cur
        float4 uv = ((const float4*)(g_u_cur + (size_t)ur * EMB))[lane];
        float4 t2[N_INT];
        float dots[N_INT];
        #pragma unroll
        for (int i = 0; i < N_INT; i++) {
            t2[i] = ((const float4*)(g_intent2 + i * EMB))[lane];
            float p = uv.x * t2[i].x + uv.y * t2[i].y + uv.z * t2[i].z + uv.w * t2[i].w;
            dots[i] = warp_sum(p);
        }
        // aggregate interactions (reads e_src = old e)
        int beg = g_ucnt[ur], end = g_ucnt[ur + 1];
        float4 acc = make_float4(0.f, 0.f, 0.f, 0.f);
        for (int k = beg; k < end; k++) {
            int c = g_icol[k];
            float v = g_ival[k];
            float4 ev = ((const float4*)(e_src + (size_t)c * EMB))[lane];
            acc.x += ev.x * v; acc.y += ev.y * v; acc.z += ev.z * v; acc.w += ev.w * v;
        }
        float mx = dots[0];
        #pragma unroll
        for (int i = 1; i < N_INT; i++) mx = fmaxf(mx, dots[i]);
        float se = 0.f;
        #pragma unroll
        for (int i = 0; i < N_INT; i++) { dots[i] = expf(dots[i] - mx); se += dots[i]; }
        float inv = 1.f / se;
        float4 w = make_float4(0.f, 0.f, 0.f, 0.f);
        #pragma unroll
        for (int i = 0; i < N_INT; i++) {
            float sc = dots[i] * inv;
            w.x += sc * t2[i].x; w.y += sc * t2[i].y; w.z += sc * t2[i].z; w.w += sc * t2[i].w;
        }
        float4 o = make_float4(acc.x * (1.f + w.x), acc.y * (1.f + w.y),
                               acc.z * (1.f + w.z), acc.w * (1.f + w.w));
        float ss = warp_sum(o.x * o.x + o.y * o.y + o.z * o.z + o.w * o.w);
        float in2 = 1.f / fmaxf(sqrtf(ss), 1e-12f);
        float4 on = make_float4(o.x * in2, o.y * in2, o.z * in2, o.w * in2);
        ((float4*)(g_u_cur + (size_t)ur * EMB))[lane] = on;
        float4* rp = (float4*)(res_u + (size_t)ur * EMB) + lane;
        float4 r = *rp;
        *rp = make_float4(r.x + on.x, r.y + on.y, r.z + on.z, r.w + on.w);
    }
}

// ---------------- launch ----------------
extern "C" void kernel_launch(void* const* d_in, const int* in_sizes, int n_in,
                              void* d_out, int out_size) {
    const float* user_emb   = (const float*)d_in[0];
    const float* entity_emb = (const float*)d_in[1];
    const float* intent_emb = (const float*)d_in[2];
    const int*   edge_index = (const int*)d_in[3];
    const int*   edge_type  = (const int*)d_in[4];
    const int*   irows      = (const int*)d_in[5];
    const int*   icols      = (const int*)d_in[6];
    const float* ivals      = (const float*)d_in[7];
    const float* r_emb      = (const float*)d_in[8];

    float* out   = (float*)d_out;
    float* res_e = out;
    float* res_u = out + (size_t)N_ENT * EMB;
    float* cor_o = out + (size_t)N_ENT * EMB + (size_t)N_USERS * EMB;

    const size_t ebytes = sizeof(float) * (size_t)N_ENT * EMB;
    const size_t ubytes = sizeof(float) * (size_t)N_USERS * EMB;

    cudaMemcpyAsync(res_e, entity_emb, ebytes, cudaMemcpyDeviceToDevice);
    cudaMemcpyAsync(res_u, user_emb,   ubytes, cudaMemcpyDeviceToDevice);
    cudaMemcpyToSymbolAsync(g_e_buf0, entity_emb, ebytes, 0, cudaMemcpyDeviceToDevice);
    cudaMemcpyToSymbolAsync(g_u_cur,  user_emb,   ubytes, 0, cudaMemcpyDeviceToDevice);

    zero_counts_kernel<<<(N_ENT + 256) / 256, 256>>>(cor_o);
    count_kernel<<<(N_EDGES + NNZ + 255) / 256, 256>>>(edge_index, irows);
    scan_kernel<<<2, 1024>>>();
    fill_kernel<<<(N_EDGES + NNZ + 255) / 256, 256>>>(edge_index, edge_type,
                                                      irows, icols, ivals);
    intent2_kernel<<<1, 128>>>(intent_emb, r_emb);
    cor_pair_kernel<<<10, 128>>>(intent_emb, cor_o);

    float* e_buf0 = nullptr; float* e_buf1 = nullptr;
    cudaGetSymbolAddress((void**)&e_buf0, g_e_buf0);
    cudaGetSymbolAddress((void**)&e_buf1, g_e_buf1);

    const int fin_total = N_ENT + N_USERS;
    const int hop_blocks = (int)(((size_t)fin_total * 32 + 255) / 256);
    // hop 0: src = buf0, dst = buf1 ; hop 1: src = buf1, dst = buf0
    hop_kernel<<<hop_blocks, 256>>>(e_buf0, e_buf1, r_emb, res_e, res_u);
    hop_kernel<<<hop_blocks, 256>>>(e_buf1, e_buf0, r_emb, res_e, res_u);

    (void)in_sizes; (void)n_in; (void)out_size;
}

// round 4
// speedup vs baseline: 1.9648x; 1.2190x over previous
#include <cuda_runtime.h>
#include <math.h>

#define N_USERS 50000
#define N_ENT   100000
#define N_INT   5
#define EMB     128
#define N_REL   20
#define N_EDGES 1000000
#define NNZ     1000000

// ---------------- scratch (device globals; no runtime allocation) ----------------
__device__ __align__(16) float g_e1[(size_t)N_ENT * EMB];     // hop-0 entity output
__device__ __align__(16) float g_u1[(size_t)N_USERS * EMB];   // hop-0 user output
__device__ __align__(16) float g_intent2[N_INT * EMB];

__device__ int g_ecnt[N_ENT + 1];    // counts -> exclusive offsets (+ total at [N])
__device__ int g_ucnt[N_USERS + 1];
__device__ int g_ecur[N_ENT];        // fill cursors
__device__ int g_ucur[N_USERS];
__device__ int   g_epay[N_EDGES];    // tail*32 + rel
__device__ int   g_icol[NNZ];
__device__ float g_ival[NNZ];

// ---------------- helpers ----------------
__device__ __forceinline__ float warp_sum(float v) {
    #pragma unroll
    for (int o = 16; o; o >>= 1) v += __shfl_xor_sync(0xffffffffu, v, o);
    return v;
}

__device__ __forceinline__ void fma4(float4& a, float4 e, float4 r) {
    a.x += e.x * r.x; a.y += e.y * r.y; a.z += e.z * r.z; a.w += e.w * r.w;
}
__device__ __forceinline__ void fma4s(float4& a, float4 e, float s) {
    a.x += e.x * s; a.y += e.y * s; a.z += e.z * s; a.w += e.w * s;
}

// ---------------- prologue ----------------
__global__ void count_kernel(const int* __restrict__ edge_index,
                             const int* __restrict__ irows) {
    int i = blockIdx.x * blockDim.x + threadIdx.x;
    if (i < N_EDGES) atomicAdd(&g_ecnt[edge_index[i]], 1);
    else if (i < N_EDGES + NNZ) atomicAdd(&g_ucnt[irows[i - N_EDGES]], 1);
}

// block 0 scans entity counts, block 1 scans user counts (1024 threads each)
__global__ void scan_kernel() {
    __shared__ int part[1024];
    int* cnt   = (blockIdx.x == 0) ? g_ecnt : g_ucnt;
    int* cur   = (blockIdx.x == 0) ? g_ecur : g_ucur;
    int  n     = (blockIdx.x == 0) ? N_ENT  : N_USERS;
    int tid = threadIdx.x;
    int chunk = (n + 1023) / 1024;
    int lo = tid * chunk;
    int hi = lo + chunk; if (hi > n) hi = n; if (lo > n) lo = n;
    int s = 0;
    for (int i = lo; i < hi; i++) s += cnt[i];
    part[tid] = s;
    __syncthreads();
    for (int off = 1; off < 1024; off <<= 1) {
        int v = part[tid];
        int add = (tid >= off) ? part[tid - off] : 0;
        __syncthreads();
        part[tid] = v + add;
        __syncthreads();
    }
    int run = (tid > 0) ? part[tid - 1] : 0;
    for (int i = lo; i < hi; i++) {
        int c = cnt[i];
        cnt[i] = run;
        cur[i] = run;
        run += c;
    }
    if (tid == 1023) cnt[n] = part[1023];
}

__global__ void fill_kernel(const int* __restrict__ edge_index,
                            const int* __restrict__ edge_type,
                            const int* __restrict__ irows,
                            const int* __restrict__ icols,
                            const float* __restrict__ ivals) {
    int i = blockIdx.x * blockDim.x + threadIdx.x;
    if (i < N_EDGES) {
        int head = edge_index[i];
        int tail = edge_index[N_EDGES + i];
        int rel  = edge_type[i] - 1;
        int pos = atomicAdd(&g_ecur[head], 1);
        g_epay[pos] = (tail << 5) | rel;
    } else if (i < N_EDGES + NNZ) {
        int k = i - N_EDGES;
        int r = irows[k];
        int pos = atomicAdd(&g_ucur[r], 1);
        g_icol[pos] = icols[k];
        g_ival[pos] = ivals[k];
    }
}

// ---------------- intent2 (hop-invariant) + zero cor ----------------
__global__ void intent2_kernel(const float* __restrict__ intent_emb,
                               const float* __restrict__ r_emb,
                               float* __restrict__ cor_o) {
    __shared__ float r[N_REL][EMB];
    __shared__ float att[N_REL];
    int tid = threadIdx.x;  // 128 threads
    if (tid == 0) *cor_o = 0.f;
    for (int i = tid; i < N_REL * EMB; i += blockDim.x)
        r[i / EMB][i % EMB] = r_emb[i];
    __syncthreads();

    const int starts[5] = {0, 0, 4, 8, 12};
    const int counts[5] = {20, 4, 4, 4, 8};

    for (int i = 0; i < N_INT; i++) {
        int s = starts[i], n = counts[i];
        if (tid < n) {
            float d = 0.f;
            #pragma unroll 4
            for (int k = 0; k < EMB; k++)
                d += intent_emb[i * EMB + k] * r[s + tid][k];
            att[tid] = d;
        }
        __syncthreads();
        if (tid == 0) {
            float mx = -1e30f;
            for (int q = 0; q < n; q++) mx = fmaxf(mx, att[q]);
            float se = 0.f;
            for (int q = 0; q < n; q++) { att[q] = expf(att[q] - mx); se += att[q]; }
            float inv = 1.f / se;
            for (int q = 0; q < n; q++) att[q] *= inv;
        }
        __syncthreads();
        {
            float acc = 0.f;
            for (int q = 0; q < n; q++) acc += att[q] * r[s + q][tid];
            acc /= (float)n;
            g_intent2[i * EMB + tid] = 0.5f * (acc + intent_emb[i * EMB + tid]);
        }
        __syncthreads();
    }
}

// ---------------- distance-correlation: one block per pair ----------------
__device__ float block_sum_128(float v, float* sh) {
    v = warp_sum(v);
    int w = threadIdx.x >> 5;
    if ((threadIdx.x & 31) == 0) sh[w] = v;
    __syncthreads();
    float r = sh[0] + sh[1] + sh[2] + sh[3];
    __syncthreads();
    return r;
}

__global__ void cor_pair_kernel(const float* __restrict__ intent_emb,
                                float* __restrict__ out_cor) {
    const int pi[10] = {0,0,0,0,1,1,1,2,2,3};
    const int pj[10] = {1,2,3,4,2,3,4,3,4,4};
    int i = pi[blockIdx.x], j = pj[blockIdx.x];

    __shared__ float ti[EMB], tj[EMB];
    __shared__ float am_a[EMB], am_b[EMB];
    __shared__ float redbuf[4];
    int tid = threadIdx.x;  // 128
    ti[tid] = intent_emb[i * EMB + tid];
    tj[tid] = intent_emb[j * EMB + tid];
    __syncthreads();

    float tik = ti[tid], tjk = tj[tid];
    float sa = 0.f, sb = 0.f;
    #pragma unroll 8
    for (int l = 0; l < EMB; l++) {
        float da = tik - ti[l];
        float db = tjk - tj[l];
        sa += sqrtf(da * da + 1e-8f);
        sb += sqrtf(db * db + 1e-8f);
    }
    am_a[tid] = sa * (1.f / EMB);
    am_b[tid] = sb * (1.f / EMB);
    __syncthreads();
    float ga = 0.f, gb = 0.f;
    #pragma unroll 8
    for (int l = 0; l < EMB; l++) { ga += am_a[l]; gb += am_b[l]; }
    ga *= (1.f / EMB); gb *= (1.f / EMB);

    float amk = am_a[tid], bmk = am_b[tid];
    float pab = 0.f, paa = 0.f, pbb = 0.f;
    #pragma unroll 8
    for (int l = 0; l < EMB; l++) {
        float da = tik - ti[l];
        float db = tjk - tj[l];
        float A = sqrtf(da * da + 1e-8f) - amk - am_a[l] + ga;
        float B = sqrtf(db * db + 1e-8f) - bmk - am_b[l] + gb;
        pab += A * B; paa += A * A; pbb += B * B;
    }
    float SAB = block_sum_128(pab, redbuf);
    float SAA = block_sum_128(paa, redbuf);
    float SBB = block_sum_128(pbb, redbuf);
    if (tid == 0) {
        const float d2 = (float)EMB * (float)EMB;
        float dAB = sqrtf(fmaxf(SAB / d2, 0.f) + 1e-8f);
        float dAA = sqrtf(fmaxf(SAA / d2, 0.f) + 1e-8f);
        float dBB = sqrtf(fmaxf(SBB / d2, 0.f) + 1e-8f);
        atomicAdd(out_cor, dAB / sqrtf(dAA * dBB + 1e-8f));
    }
}

// ---------------- gather cores (4-wide unroll for MLP) ----------------
__device__ __forceinline__ float4 gather_entity(const float* __restrict__ e_src,
                                                const float* __restrict__ r_emb,
                                                int beg, int end, unsigned lane) {
    float4 acc = make_float4(0.f, 0.f, 0.f, 0.f);
    int k = beg;
    for (; k + 4 <= end; k += 4) {
        int p0 = g_epay[k], p1 = g_epay[k+1], p2 = g_epay[k+2], p3 = g_epay[k+3];
        float4 e0 = ((const float4*)(e_src + (size_t)(p0 >> 5) * EMB))[lane];
        float4 e1 = ((const float4*)(e_src + (size_t)(p1 >> 5) * EMB))[lane];
        float4 e2 = ((const float4*)(e_src + (size_t)(p2 >> 5) * EMB))[lane];
        float4 e3 = ((const float4*)(e_src + (size_t)(p3 >> 5) * EMB))[lane];
        float4 r0 = ((const float4*)(r_emb + (size_t)(p0 & 31) * EMB))[lane];
        float4 r1 = ((const float4*)(r_emb + (size_t)(p1 & 31) * EMB))[lane];
        float4 r2 = ((const float4*)(r_emb + (size_t)(p2 & 31) * EMB))[lane];
        float4 r3 = ((const float4*)(r_emb + (size_t)(p3 & 31) * EMB))[lane];
        fma4(acc, e0, r0); fma4(acc, e1, r1); fma4(acc, e2, r2); fma4(acc, e3, r3);
    }
    for (; k < end; k++) {
        int p = g_epay[k];
        float4 ev = ((const float4*)(e_src + (size_t)(p >> 5) * EMB))[lane];
        float4 rv = ((const float4*)(r_emb + (size_t)(p & 31) * EMB))[lane];
        fma4(acc, ev, rv);
    }
    return acc;
}

__device__ __forceinline__ float4 gather_user(const float* __restrict__ e_src,
                                              int beg, int end, unsigned lane) {
    float4 acc = make_float4(0.f, 0.f, 0.f, 0.f);
    int k = beg;
    for (; k + 4 <= end; k += 4) {
        int c0 = g_icol[k], c1 = g_icol[k+1], c2 = g_icol[k+2], c3 = g_icol[k+3];
        float v0 = g_ival[k], v1 = g_ival[k+1], v2 = g_ival[k+2], v3 = g_ival[k+3];
        float4 e0 = ((const float4*)(e_src + (size_t)c0 * EMB))[lane];
        float4 e1 = ((const float4*)(e_src + (size_t)c1 * EMB))[lane];
        float4 e2 = ((const float4*)(e_src + (size_t)c2 * EMB))[lane];
        float4 e3 = ((const float4*)(e_src + (size_t)c3 * EMB))[lane];
        fma4s(acc, e0, v0); fma4s(acc, e1, v1); fma4s(acc, e2, v2); fma4s(acc, e3, v3);
    }
    for (; k < end; k++) {
        float4 ev = ((const float4*)(e_src + (size_t)g_icol[k] * EMB))[lane];
        fma4s(acc, ev, g_ival[k]);
    }
    return acc;
}

__device__ __forceinline__ float4 user_epilogue(float4 acc, float4 uv, unsigned lane) {
    // score softmax over intents from uv, then o = acc * (1 + score@intent2), L2-norm
    float4 t2[N_INT];
    float dots[N_INT];
    #pragma unroll
    for (int i = 0; i < N_INT; i++) {
        t2[i] = ((const float4*)(g_intent2 + i * EMB))[lane];
        float p = uv.x * t2[i].x + uv.y * t2[i].y + uv.z * t2[i].z + uv.w * t2[i].w;
        dots[i] = warp_sum(p);
    }
    float mx = dots[0];
    #pragma unroll
    for (int i = 1; i < N_INT; i++) mx = fmaxf(mx, dots[i]);
    float se = 0.f;
    #pragma unroll
    for (int i = 0; i < N_INT; i++) { dots[i] = expf(dots[i] - mx); se += dots[i]; }
    float inv = 1.f / se;
    float4 w = make_float4(0.f, 0.f, 0.f, 0.f);
    #pragma unroll
    for (int i = 0; i < N_INT; i++) {
        float sc = dots[i] * inv;
        fma4s(w, t2[i], sc);
    }
    float4 o = make_float4(acc.x * (1.f + w.x), acc.y * (1.f + w.y),
                           acc.z * (1.f + w.z), acc.w * (1.f + w.w));
    float ss = warp_sum(o.x * o.x + o.y * o.y + o.z * o.z + o.w * o.w);
    float in2 = 1.f / fmaxf(sqrtf(ss), 1e-12f);
    return make_float4(o.x * in2, o.y * in2, o.z * in2, o.w * in2);
}

__device__ __forceinline__ float4 l2norm4(float4 v) {
    float ss = warp_sum(v.x * v.x + v.y * v.y + v.z * v.z + v.w * v.w);
    float in2 = 1.f / fmaxf(sqrtf(ss), 1e-12f);
    return make_float4(v.x * in2, v.y * in2, v.z * in2, v.w * in2);
}

// ---------------- hop 0: inputs -> (g_e1, g_u1); no residual writes ----------------
__global__ void hop0_kernel(const float* __restrict__ entity_emb,
                            const float* __restrict__ user_emb,
                            const float* __restrict__ r_emb) {
    unsigned gid = blockIdx.x * blockDim.x + threadIdx.x;
    unsigned row = gid >> 5, lane = gid & 31;
    if (row < N_ENT) {
        int beg = g_ecnt[row], end = g_ecnt[row + 1];
        float4 acc = gather_entity(entity_emb, r_emb, beg, end, lane);
        int cnt = end - beg;
        float inv = (cnt > 0) ? (1.f / (float)cnt) : 0.f;
        float4 v = make_float4(acc.x * inv, acc.y * inv, acc.z * inv, acc.w * inv);
        ((float4*)(g_e1 + (size_t)row * EMB))[lane] = l2norm4(v);
    } else if (row < N_ENT + N_USERS) {
        unsigned ur = row - N_ENT;
        float4 uv = ((const float4*)(user_emb + (size_t)ur * EMB))[lane];
        int beg = g_ucnt[ur], end = g_ucnt[ur + 1];
        float4 acc = gather_user(entity_emb, beg, end, lane);
        ((float4*)(g_u1 + (size_t)ur * EMB))[lane] = user_epilogue(acc, uv, lane);
    }
}

// ---------------- hop 1: (g_e1, g_u1) -> residuals in d_out ----------------
__global__ void hop1_kernel(const float* __restrict__ entity_emb,
                            const float* __restrict__ user_emb,
                            const float* __restrict__ r_emb,
                            float* __restrict__ res_e,
                            float* __restrict__ res_u) {
    unsigned gid = blockIdx.x * blockDim.x + threadIdx.x;
    unsigned row = gid >> 5, lane = gid & 31;
    if (row < N_ENT) {
        int beg = g_ecnt[row], end = g_ecnt[row + 1];
        float4 acc = gather_entity(g_e1, r_emb, beg, end, lane);
        int cnt = end - beg;
        float inv = (cnt > 0) ? (1.f / (float)cnt) : 0.f;
        float4 v = make_float4(acc.x * inv, acc.y * inv, acc.z * inv, acc.w * inv);
        float4 vn = l2norm4(v);
        float4 e0 = ((const float4*)(entity_emb + (size_t)row * EMB))[lane];
        float4 e1 = ((const float4*)(g_e1 + (size_t)row * EMB))[lane];
        ((float4*)(res_e + (size_t)row * EMB))[lane] =
            make_float4(e0.x + e1.x + vn.x, e0.y + e1.y + vn.y,
                        e0.z + e1.z + vn.z, e0.w + e1.w + vn.w);
    } else if (row < N_ENT + N_USERS) {
        unsigned ur = row - N_ENT;
        float4 uv = ((const float4*)(g_u1 + (size_t)ur * EMB))[lane];  // u1: score + residual
        int beg = g_ucnt[ur], end = g_ucnt[ur + 1];
        float4 acc = gather_user(g_e1, beg, end, lane);
        float4 on = user_epilogue(acc, uv, lane);
        float4 u0 = ((const float4*)(user_emb + (size_t)ur * EMB))[lane];
        ((float4*)(res_u + (size_t)ur * EMB))[lane] =
            make_float4(u0.x + uv.x + on.x, u0.y + uv.y + on.y,
                        u0.z + uv.z + on.z, u0.w + uv.w + on.w);
    }
}

// ---------------- launch ----------------
extern "C" void kernel_launch(void* const* d_in, const int* in_sizes, int n_in,
                              void* d_out, int out_size) {
    const float* user_emb   = (const float*)d_in[0];
    const float* entity_emb = (const float*)d_in[1];
    const float* intent_emb = (const float*)d_in[2];
    const int*   edge_index = (const int*)d_in[3];
    const int*   edge_type  = (const int*)d_in[4];
    const int*   irows      = (const int*)d_in[5];
    const int*   icols      = (const int*)d_in[6];
    const float* ivals      = (const float*)d_in[7];
    const float* r_emb      = (const float*)d_in[8];

    float* out   = (float*)d_out;
    float* res_e = out;
    float* res_u = out + (size_t)N_ENT * EMB;
    float* cor_o = out + (size_t)N_ENT * EMB + (size_t)N_USERS * EMB;

    void* p_ecnt = nullptr; void* p_ucnt = nullptr;
    cudaGetSymbolAddress(&p_ecnt, g_ecnt);
    cudaGetSymbolAddress(&p_ucnt, g_ucnt);
    cudaMemsetAsync(p_ecnt, 0, sizeof(int) * (N_ENT + 1));
    cudaMemsetAsync(p_ucnt, 0, sizeof(int) * (N_USERS + 1));

    count_kernel<<<(N_EDGES + NNZ + 255) / 256, 256>>>(edge_index, irows);
    scan_kernel<<<2, 1024>>>();
    fill_kernel<<<(N_EDGES + NNZ + 255) / 256, 256>>>(edge_index, edge_type,
                                                      irows, icols, ivals);
    intent2_kernel<<<1, 128>>>(intent_emb, r_emb, cor_o);
    cor_pair_kernel<<<10, 128>>>(intent_emb, cor_o);

    const int fin_total = N_ENT + N_USERS;
    const int hop_blocks = (int)(((size_t)fin_total * 32 + 255) / 256);
    hop0_kernel<<<hop_blocks, 256>>>(entity_emb, user_emb, r_emb);
    hop1_kernel<<<hop_blocks, 256>>>(entity_emb, user_emb, r_emb, res_e, res_u);

    (void)in_sizes; (void)n_in; (void)out_size;
}

// round 5
// speedup vs baseline: 2.2627x; 1.1516x over previous
#include <cuda_runtime.h>
#include <math.h>

#define N_USERS 50000
#define N_ENT   100000
#define N_INT   5
#define EMB     128
#define N_REL   20
#define N_EDGES 1000000
#define NNZ     1000000

// ---------------- scratch (device globals; no runtime allocation) ----------------
__device__ __align__(16) float g_e1[(size_t)N_ENT * EMB];     // hop-0 entity output
__device__ __align__(16) float g_u1[(size_t)N_USERS * EMB];   // hop-0 user output
__device__ __align__(16) float g_intent2[N_INT * EMB];

__device__ int g_ecnt[N_ENT + 1];    // counts -> exclusive offsets (+ total at [N])
__device__ int g_ucnt[N_USERS + 1];
__device__ int g_ecur[N_ENT];        // fill cursors
__device__ int g_ucur[N_USERS];
__device__ int   g_epay[N_EDGES];    // tail*32 + rel
__device__ int   g_icol[NNZ];
__device__ float g_ival[NNZ];

// ---------------- helpers ----------------
__device__ __forceinline__ float warp_sum(float v) {
    #pragma unroll
    for (int o = 16; o; o >>= 1) v += __shfl_xor_sync(0xffffffffu, v, o);
    return v;
}

__device__ __forceinline__ void fma4(float4& a, float4 e, float4 r) {
    a.x += e.x * r.x; a.y += e.y * r.y; a.z += e.z * r.z; a.w += e.w * r.w;
}
__device__ __forceinline__ void fma4s(float4& a, float4 e, float s) {
    a.x += e.x * s; a.y += e.y * s; a.z += e.z * s; a.w += e.w * s;
}

// ---------------- prologue ----------------
__global__ void count_kernel(const int* __restrict__ edge_index,
                             const int* __restrict__ irows) {
    int i = blockIdx.x * blockDim.x + threadIdx.x;
    if (i < N_EDGES) atomicAdd(&g_ecnt[edge_index[i]], 1);
    else if (i < N_EDGES + NNZ) atomicAdd(&g_ucnt[irows[i - N_EDGES]], 1);
}

// block 0 scans entity counts, block 1 scans user counts (1024 threads each)
__global__ void scan_kernel() {
    __shared__ int part[1024];
    int* cnt   = (blockIdx.x == 0) ? g_ecnt : g_ucnt;
    int* cur   = (blockIdx.x == 0) ? g_ecur : g_ucur;
    int  n     = (blockIdx.x == 0) ? N_ENT  : N_USERS;
    int tid = threadIdx.x;
    int chunk = (n + 1023) / 1024;
    int lo = tid * chunk;
    int hi = lo + chunk; if (hi > n) hi = n; if (lo > n) lo = n;
    int s = 0;
    for (int i = lo; i < hi; i++) s += cnt[i];
    part[tid] = s;
    __syncthreads();
    for (int off = 1; off < 1024; off <<= 1) {
        int v = part[tid];
        int add = (tid >= off) ? part[tid - off] : 0;
        __syncthreads();
        part[tid] = v + add;
        __syncthreads();
    }
    int run = (tid > 0) ? part[tid - 1] : 0;
    for (int i = lo; i < hi; i++) {
        int c = cnt[i];
        cnt[i] = run;
        cur[i] = run;
        run += c;
    }
    if (tid == 1023) cnt[n] = part[1023];
}

__global__ void fill_kernel(const int* __restrict__ edge_index,
                            const int* __restrict__ edge_type,
                            const int* __restrict__ irows,
                            const int* __restrict__ icols,
                            const float* __restrict__ ivals) {
    int i = blockIdx.x * blockDim.x + threadIdx.x;
    if (i < N_EDGES) {
        int head = edge_index[i];
        int tail = edge_index[N_EDGES + i];
        int rel  = edge_type[i] - 1;
        int pos = atomicAdd(&g_ecur[head], 1);
        g_epay[pos] = (tail << 5) | rel;
    } else if (i < N_EDGES + NNZ) {
        int k = i - N_EDGES;
        int r = irows[k];
        int pos = atomicAdd(&g_ucur[r], 1);
        g_icol[pos] = icols[k];
        g_ival[pos] = ivals[k];
    }
}

// ---------------- merged small-work kernel: block 0 intent2, blocks 1-10 cor ------
__device__ float block_sum_128(float v, float* sh) {
    v = warp_sum(v);
    int w = threadIdx.x >> 5;
    if ((threadIdx.x & 31) == 0) sh[w] = v;
    __syncthreads();
    float r = sh[0] + sh[1] + sh[2] + sh[3];
    __syncthreads();
    return r;
}

__global__ void intent_cor_kernel(const float* __restrict__ intent_emb,
                                  const float* __restrict__ r_emb,
                                  float* __restrict__ out_cor) {
    int tid = threadIdx.x;  // 128
    int lane = tid & 31, wid = tid >> 5;

    if (blockIdx.x == 0) {
        // ---------- intent2 ----------
        __shared__ float r[N_REL][EMB];
        __shared__ float ie[N_INT][EMB];
        __shared__ float att[N_REL];
        for (int i = tid; i < N_REL * EMB; i += 128)
            r[i / EMB][i % EMB] = r_emb[i];
        for (int i = tid; i < N_INT * EMB; i += 128)
            ie[i / EMB][i % EMB] = intent_emb[i];
        __syncthreads();

        const int starts[5] = {0, 0, 4, 8, 12};
        const int counts[5] = {20, 4, 4, 4, 8};

        for (int i = 0; i < N_INT; i++) {
            int s = starts[i], n = counts[i];
            // one warp per relation dot, stride 4 warps
            for (int rel = wid; rel < n; rel += 4) {
                float d = 0.f;
                #pragma unroll
                for (int t = 0; t < 4; t++)
                    d += ie[i][lane * 4 + t] * r[s + rel][lane * 4 + t];
                d = warp_sum(d);
                if (lane == 0) att[rel] = d;
            }
            __syncthreads();
            if (tid == 0) {
                float mx = -1e30f;
                for (int q = 0; q < n; q++) mx = fmaxf(mx, att[q]);
                float se = 0.f;
                for (int q = 0; q < n; q++) { att[q] = expf(att[q] - mx); se += att[q]; }
                float inv = 1.f / se;
                for (int q = 0; q < n; q++) att[q] *= inv;
            }
            __syncthreads();
            {
                float acc = 0.f;
                for (int q = 0; q < n; q++) acc += att[q] * r[s + q][tid];
                acc /= (float)n;
                g_intent2[i * EMB + tid] = 0.5f * (acc + ie[i][tid]);
            }
            __syncthreads();
        }
    } else {
        // ---------- distance correlation, one pair per block ----------
        const int pi[10] = {0,0,0,0,1,1,1,2,2,3};
        const int pj[10] = {1,2,3,4,2,3,4,3,4,4};
        int i = pi[blockIdx.x - 1], j = pj[blockIdx.x - 1];

        __shared__ float ti[EMB], tj[EMB];
        __shared__ float am_a[EMB], am_b[EMB];
        __shared__ float redbuf[4];
        ti[tid] = intent_emb[i * EMB + tid];
        tj[tid] = intent_emb[j * EMB + tid];
        __syncthreads();

        float tik = ti[tid], tjk = tj[tid];
        float sa = 0.f, sb = 0.f;
        #pragma unroll 8
        for (int l = 0; l < EMB; l++) {
            float da = tik - ti[l];
            float db = tjk - tj[l];
            sa += sqrtf(da * da + 1e-8f);
            sb += sqrtf(db * db + 1e-8f);
        }
        am_a[tid] = sa * (1.f / EMB);
        am_b[tid] = sb * (1.f / EMB);
        __syncthreads();
        float ga = 0.f, gb = 0.f;
        #pragma unroll 8
        for (int l = 0; l < EMB; l++) { ga += am_a[l]; gb += am_b[l]; }
        ga *= (1.f / EMB); gb *= (1.f / EMB);

        float amk = am_a[tid], bmk = am_b[tid];
        float pab = 0.f, paa = 0.f, pbb = 0.f;
        #pragma unroll 8
        for (int l = 0; l < EMB; l++) {
            float da = tik - ti[l];
            float db = tjk - tj[l];
            float A = sqrtf(da * da + 1e-8f) - amk - am_a[l] + ga;
            float B = sqrtf(db * db + 1e-8f) - bmk - am_b[l] + gb;
            pab += A * B; paa += A * A; pbb += B * B;
        }
        float SAB = block_sum_128(pab, redbuf);
        float SAA = block_sum_128(paa, redbuf);
        float SBB = block_sum_128(pbb, redbuf);
        if (tid == 0) {
            const float d2 = (float)EMB * (float)EMB;
            float dAB = sqrtf(fmaxf(SAB / d2, 0.f) + 1e-8f);
            float dAA = sqrtf(fmaxf(SAA / d2, 0.f) + 1e-8f);
            float dBB = sqrtf(fmaxf(SBB / d2, 0.f) + 1e-8f);
            atomicAdd(out_cor, dAB / sqrtf(dAA * dBB + 1e-8f));
        }
    }
}

// ---------------- gather cores (4-wide unroll for MLP) ----------------
__device__ __forceinline__ float4 gather_entity(const float* __restrict__ e_src,
                                                const float* __restrict__ r_emb,
                                                int beg, int end, unsigned lane) {
    float4 acc = make_float4(0.f, 0.f, 0.f, 0.f);
    int k = beg;
    #pragma unroll 1
    for (; k + 4 <= end; k += 4) {
        int p0 = g_epay[k], p1 = g_epay[k+1], p2 = g_epay[k+2], p3 = g_epay[k+3];
        float4 e0 = ((const float4*)(e_src + (size_t)(p0 >> 5) * EMB))[lane];
        float4 e1 = ((const float4*)(e_src + (size_t)(p1 >> 5) * EMB))[lane];
        float4 e2 = ((const float4*)(e_src + (size_t)(p2 >> 5) * EMB))[lane];
        float4 e3 = ((const float4*)(e_src + (size_t)(p3 >> 5) * EMB))[lane];
        float4 r0 = ((const float4*)(r_emb + (size_t)(p0 & 31) * EMB))[lane];
        float4 r1 = ((const float4*)(r_emb + (size_t)(p1 & 31) * EMB))[lane];
        float4 r2 = ((const float4*)(r_emb + (size_t)(p2 & 31) * EMB))[lane];
        float4 r3 = ((const float4*)(r_emb + (size_t)(p3 & 31) * EMB))[lane];
        fma4(acc, e0, r0); fma4(acc, e1, r1); fma4(acc, e2, r2); fma4(acc, e3, r3);
    }
    #pragma unroll 1
    for (; k < end; k++) {
        int p = g_epay[k];
        float4 ev = ((const float4*)(e_src + (size_t)(p >> 5) * EMB))[lane];
        float4 rv = ((const float4*)(r_emb + (size_t)(p & 31) * EMB))[lane];
        fma4(acc, ev, rv);
    }
    return acc;
}

__device__ __forceinline__ float4 gather_user(const float* __restrict__ e_src,
                                              int beg, int end, unsigned lane) {
    float4 acc = make_float4(0.f, 0.f, 0.f, 0.f);
    int k = beg;
    #pragma unroll 1
    for (; k + 4 <= end; k += 4) {
        int c0 = g_icol[k], c1 = g_icol[k+1], c2 = g_icol[k+2], c3 = g_icol[k+3];
        float v0 = g_ival[k], v1 = g_ival[k+1], v2 = g_ival[k+2], v3 = g_ival[k+3];
        float4 e0 = ((const float4*)(e_src + (size_t)c0 * EMB))[lane];
        float4 e1 = ((const float4*)(e_src + (size_t)c1 * EMB))[lane];
        float4 e2 = ((const float4*)(e_src + (size_t)c2 * EMB))[lane];
        float4 e3 = ((const float4*)(e_src + (size_t)c3 * EMB))[lane];
        fma4s(acc, e0, v0); fma4s(acc, e1, v1); fma4s(acc, e2, v2); fma4s(acc, e3, v3);
    }
    #pragma unroll 1
    for (; k < end; k++) {
        float4 ev = ((const float4*)(e_src + (size_t)g_icol[k] * EMB))[lane];
        fma4s(acc, ev, g_ival[k]);
    }
    return acc;
}

__device__ __forceinline__ float4 user_epilogue(float4 acc, float4 uv, unsigned lane) {
    float4 t2[N_INT];
    float dots[N_INT];
    #pragma unroll
    for (int i = 0; i < N_INT; i++) {
        t2[i] = ((const float4*)(g_intent2 + i * EMB))[lane];
        float p = uv.x * t2[i].x + uv.y * t2[i].y + uv.z * t2[i].z + uv.w * t2[i].w;
        dots[i] = warp_sum(p);
    }
    float mx = dots[0];
    #pragma unroll
    for (int i = 1; i < N_INT; i++) mx = fmaxf(mx, dots[i]);
    float se = 0.f;
    #pragma unroll
    for (int i = 0; i < N_INT; i++) { dots[i] = expf(dots[i] - mx); se += dots[i]; }
    float inv = 1.f / se;
    float4 w = make_float4(0.f, 0.f, 0.f, 0.f);
    #pragma unroll
    for (int i = 0; i < N_INT; i++) {
        float sc = dots[i] * inv;
        fma4s(w, t2[i], sc);
    }
    float4 o = make_float4(acc.x * (1.f + w.x), acc.y * (1.f + w.y),
                           acc.z * (1.f + w.z), acc.w * (1.f + w.w));
    float ss = warp_sum(o.x * o.x + o.y * o.y + o.z * o.z + o.w * o.w);
    float in2 = 1.f / fmaxf(sqrtf(ss), 1e-12f);
    return make_float4(o.x * in2, o.y * in2, o.z * in2, o.w * in2);
}

__device__ __forceinline__ float4 l2norm4(float4 v) {
    float ss = warp_sum(v.x * v.x + v.y * v.y + v.z * v.z + v.w * v.w);
    float in2 = 1.f / fmaxf(sqrtf(ss), 1e-12f);
    return make_float4(v.x * in2, v.y * in2, v.z * in2, v.w * in2);
}

// ---------------- hop 0: inputs -> (g_e1, g_u1); no residual writes ----------------
__global__ void hop0_kernel(const float* __restrict__ entity_emb,
                            const float* __restrict__ user_emb,
                            const float* __restrict__ r_emb) {
    unsigned gid = blockIdx.x * blockDim.x + threadIdx.x;
    unsigned row = gid >> 5, lane = gid & 31;
    if (row < N_ENT) {
        int beg = g_ecnt[row], end = g_ecnt[row + 1];
        float4 acc = gather_entity(entity_emb, r_emb, beg, end, lane);
        int cnt = end - beg;
        float inv = (cnt > 0) ? (1.f / (float)cnt) : 0.f;
        float4 v = make_float4(acc.x * inv, acc.y * inv, acc.z * inv, acc.w * inv);
        ((float4*)(g_e1 + (size_t)row * EMB))[lane] = l2norm4(v);
    } else if (row < N_ENT + N_USERS) {
        unsigned ur = row - N_ENT;
        float4 uv = ((const float4*)(user_emb + (size_t)ur * EMB))[lane];
        int beg = g_ucnt[ur], end = g_ucnt[ur + 1];
        float4 acc = gather_user(entity_emb, beg, end, lane);
        ((float4*)(g_u1 + (size_t)ur * EMB))[lane] = user_epilogue(acc, uv, lane);
    }
}

// ---------------- hop 1: (g_e1, g_u1) -> residuals in d_out ----------------
__global__ void hop1_kernel(const float* __restrict__ entity_emb,
                            const float* __restrict__ user_emb,
                            const float* __restrict__ r_emb,
                            float* __restrict__ res_e,
                            float* __restrict__ res_u) {
    unsigned gid = blockIdx.x * blockDim.x + threadIdx.x;
    unsigned row = gid >> 5, lane = gid & 31;
    if (row < N_ENT) {
        int beg = g_ecnt[row], end = g_ecnt[row + 1];
        float4 acc = gather_entity(g_e1, r_emb, beg, end, lane);
        int cnt = end - beg;
        float inv = (cnt > 0) ? (1.f / (float)cnt) : 0.f;
        float4 v = make_float4(acc.x * inv, acc.y * inv, acc.z * inv, acc.w * inv);
        float4 vn = l2norm4(v);
        float4 e0 = ((const float4*)(entity_emb + (size_t)row * EMB))[lane];
        float4 e1 = ((const float4*)(g_e1 + (size_t)row * EMB))[lane];
        ((float4*)(res_e + (size_t)row * EMB))[lane] =
            make_float4(e0.x + e1.x + vn.x, e0.y + e1.y + vn.y,
                        e0.z + e1.z + vn.z, e0.w + e1.w + vn.w);
    } else if (row < N_ENT + N_USERS) {
        unsigned ur = row - N_ENT;
        float4 uv = ((const float4*)(g_u1 + (size_t)ur * EMB))[lane];
        int beg = g_ucnt[ur], end = g_ucnt[ur + 1];
        float4 acc = gather_user(g_e1, beg, end, lane);
        float4 on = user_epilogue(acc, uv, lane);
        float4 u0 = ((const float4*)(user_emb + (size_t)ur * EMB))[lane];
        ((float4*)(res_u + (size_t)ur * EMB))[lane] =
            make_float4(u0.x + uv.x + on.x, u0.y + uv.y + on.y,
                        u0.z + uv.z + on.z, u0.w + uv.w + on.w);
    }
}

// ---------------- launch ----------------
extern "C" void kernel_launch(void* const* d_in, const int* in_sizes, int n_in,
                              void* d_out, int out_size) {
    const float* user_emb   = (const float*)d_in[0];
    const float* entity_emb = (const float*)d_in[1];
    const float* intent_emb = (const float*)d_in[2];
    const int*   edge_index = (const int*)d_in[3];
    const int*   edge_type  = (const int*)d_in[4];
    const int*   irows      = (const int*)d_in[5];
    const int*   icols      = (const int*)d_in[6];
    const float* ivals      = (const float*)d_in[7];
    const float* r_emb      = (const float*)d_in[8];

    float* out   = (float*)d_out;
    float* res_e = out;
    float* res_u = out + (size_t)N_ENT * EMB;
    float* cor_o = out + (size_t)N_ENT * EMB + (size_t)N_USERS * EMB;

    static cudaStream_t s2 = nullptr;
    static cudaEvent_t ev_fork = nullptr, ev_join = nullptr;
    if (!s2) {
        cudaStreamCreate(&s2);
        cudaEventCreateWithFlags(&ev_fork, cudaEventDisableTiming);
        cudaEventCreateWithFlags(&ev_join, cudaEventDisableTiming);
    }

    void* p_ecnt = nullptr; void* p_ucnt = nullptr;
    cudaGetSymbolAddress(&p_ecnt, g_ecnt);
    cudaGetSymbolAddress(&p_ucnt, g_ucnt);

    // fork side stream: intent2 + cor (independent of CSR build)
    cudaEventRecord(ev_fork, 0);
    cudaStreamWaitEvent(s2, ev_fork, 0);
    cudaMemsetAsync(cor_o, 0, sizeof(float), s2);
    intent_cor_kernel<<<11, 128, 0, s2>>>(intent_emb, r_emb, cor_o);
    cudaEventRecord(ev_join, s2);

    // main chain: CSR build
    cudaMemsetAsync(p_ecnt, 0, sizeof(int) * (N_ENT + 1));
    cudaMemsetAsync(p_ucnt, 0, sizeof(int) * (N_USERS + 1));
    count_kernel<<<(N_EDGES + NNZ + 255) / 256, 256>>>(edge_index, irows);
    scan_kernel<<<2, 1024>>>();
    fill_kernel<<<(N_EDGES + NNZ + 255) / 256, 256>>>(edge_index, edge_type,
                                                      irows, icols, ivals);

    // join before hops (hop0 user path reads g_intent2)
    cudaStreamWaitEvent(0, ev_join, 0);

    const int fin_total = N_ENT + N_USERS;
    const int hop_blocks = (int)(((size_t)fin_total * 32 + 255) / 256);
    hop0_kernel<<<hop_blocks, 256>>>(entity_emb, user_emb, r_emb);
    hop1_kernel<<<hop_blocks, 256>>>(entity_emb, user_emb, r_emb, res_e, res_u);

    (void)in_sizes; (void)n_in; (void)out_size;
}

// round 6
// speedup vs baseline: 2.3497x; 1.0384x over previous
#include <cuda_runtime.h>
#include <math.h>

#define N_USERS 50000
#define N_ENT   100000
#define N_INT   5
#define EMB     128
#define N_REL   20
#define N_EDGES 1000000
#define NNZ     1000000

// ---------------- scratch (device globals; no runtime allocation) ----------------
__device__ __align__(16) float g_e1[(size_t)N_ENT * EMB];     // hop-0 entity output
__device__ __align__(16) float g_u1[(size_t)N_USERS * EMB];   // hop-0 user output
__device__ __align__(16) float g_intent2[N_INT * EMB];

__device__ int g_ecnt[N_ENT + 1];
__device__ int g_ucnt[N_USERS + 1];
__device__ int g_ecur[N_ENT];
__device__ int g_ucur[N_USERS];
__device__ int   g_epay[N_EDGES];    // tail*32 + rel
__device__ int   g_icol[NNZ];
__device__ float g_ival[NNZ];

// ---------------- helpers ----------------
__device__ __forceinline__ float warp_sum(float v) {
    #pragma unroll
    for (int o = 16; o; o >>= 1) v += __shfl_xor_sync(0xffffffffu, v, o);
    return v;
}
__device__ __forceinline__ void fma4(float4& a, float4 e, float4 r) {
    a.x += e.x * r.x; a.y += e.y * r.y; a.z += e.z * r.z; a.w += e.w * r.w;
}
__device__ __forceinline__ void fma4s(float4& a, float4 e, float s) {
    a.x += e.x * s; a.y += e.y * s; a.z += e.z * s; a.w += e.w * s;
}

// ---------------- CSR build (per side) ----------------
__global__ void count_e_kernel(const int* __restrict__ edge_index) {
    int i = blockIdx.x * blockDim.x + threadIdx.x;
    if (i < N_EDGES) atomicAdd(&g_ecnt[edge_index[i]], 1);
}
__global__ void count_u_kernel(const int* __restrict__ irows) {
    int i = blockIdx.x * blockDim.x + threadIdx.x;
    if (i < NNZ) atomicAdd(&g_ucnt[irows[i]], 1);
}

__global__ void scan_side_kernel(int* __restrict__ cnt, int* __restrict__ cur, int n) {
    __shared__ int part[1024];
    int tid = threadIdx.x;
    int chunk = (n + 1023) / 1024;
    int lo = tid * chunk;
    int hi = lo + chunk; if (hi > n) hi = n; if (lo > n) lo = n;
    int s = 0;
    for (int i = lo; i < hi; i++) s += cnt[i];
    part[tid] = s;
    __syncthreads();
    for (int off = 1; off < 1024; off <<= 1) {
        int v = part[tid];
        int add = (tid >= off) ? part[tid - off] : 0;
        __syncthreads();
        part[tid] = v + add;
        __syncthreads();
    }
    int run = (tid > 0) ? part[tid - 1] : 0;
    for (int i = lo; i < hi; i++) {
        int c = cnt[i];
        cnt[i] = run;
        cur[i] = run;
        run += c;
    }
    if (tid == 1023) cnt[n] = part[1023];
}

__global__ void fill_e_kernel(const int* __restrict__ edge_index,
                              const int* __restrict__ edge_type) {
    int i = blockIdx.x * blockDim.x + threadIdx.x;
    if (i >= N_EDGES) return;
    int head = edge_index[i];
    int tail = edge_index[N_EDGES + i];
    int rel  = edge_type[i] - 1;
    int pos = atomicAdd(&g_ecur[head], 1);
    g_epay[pos] = (tail << 5) | rel;
}
__global__ void fill_u_kernel(const int* __restrict__ irows,
                              const int* __restrict__ icols,
                              const float* __restrict__ ivals) {
    int i = blockIdx.x * blockDim.x + threadIdx.x;
    if (i >= NNZ) return;
    int r = irows[i];
    int pos = atomicAdd(&g_ucur[r], 1);
    g_icol[pos] = icols[i];
    g_ival[pos] = ivals[i];
}

// ---------------- merged small-work kernel: block 0 intent2, blocks 1-10 cor ------
__device__ float block_sum_128(float v, float* sh) {
    v = warp_sum(v);
    int w = threadIdx.x >> 5;
    if ((threadIdx.x & 31) == 0) sh[w] = v;
    __syncthreads();
    float r = sh[0] + sh[1] + sh[2] + sh[3];
    __syncthreads();
    return r;
}

__global__ void intent_cor_kernel(const float* __restrict__ intent_emb,
                                  const float* __restrict__ r_emb,
                                  float* __restrict__ out_cor) {
    int tid = threadIdx.x;  // 128
    int lane = tid & 31, wid = tid >> 5;

    if (blockIdx.x == 0) {
        __shared__ float r[N_REL][EMB];
        __shared__ float ie[N_INT][EMB];
        __shared__ float att[N_REL];
        for (int i = tid; i < N_REL * EMB; i += 128)
            r[i / EMB][i % EMB] = r_emb[i];
        for (int i = tid; i < N_INT * EMB; i += 128)
            ie[i / EMB][i % EMB] = intent_emb[i];
        __syncthreads();

        const int starts[5] = {0, 0, 4, 8, 12};
        const int counts[5] = {20, 4, 4, 4, 8};

        for (int i = 0; i < N_INT; i++) {
            int s = starts[i], n = counts[i];
            for (int rel = wid; rel < n; rel += 4) {
                float d = 0.f;
                #pragma unroll
                for (int t = 0; t < 4; t++)
                    d += ie[i][lane * 4 + t] * r[s + rel][lane * 4 + t];
                d = warp_sum(d);
                if (lane == 0) att[rel] = d;
            }
            __syncthreads();
            if (tid == 0) {
                float mx = -1e30f;
                for (int q = 0; q < n; q++) mx = fmaxf(mx, att[q]);
                float se = 0.f;
                for (int q = 0; q < n; q++) { att[q] = expf(att[q] - mx); se += att[q]; }
                float inv = 1.f / se;
                for (int q = 0; q < n; q++) att[q] *= inv;
            }
            __syncthreads();
            {
                float acc = 0.f;
                for (int q = 0; q < n; q++) acc += att[q] * r[s + q][tid];
                acc /= (float)n;
                g_intent2[i * EMB + tid] = 0.5f * (acc + ie[i][tid]);
            }
            __syncthreads();
        }
    } else {
        const int pi[10] = {0,0,0,0,1,1,1,2,2,3};
        const int pj[10] = {1,2,3,4,2,3,4,3,4,4};
        int i = pi[blockIdx.x - 1], j = pj[blockIdx.x - 1];

        __shared__ float ti[EMB], tj[EMB];
        __shared__ float am_a[EMB], am_b[EMB];
        __shared__ float redbuf[4];
        ti[tid] = intent_emb[i * EMB + tid];
        tj[tid] = intent_emb[j * EMB + tid];
        __syncthreads();

        float tik = ti[tid], tjk = tj[tid];
        float sa = 0.f, sb = 0.f;
        #pragma unroll 8
        for (int l = 0; l < EMB; l++) {
            float da = tik - ti[l];
            float db = tjk - tj[l];
            sa += sqrtf(da * da + 1e-8f);
            sb += sqrtf(db * db + 1e-8f);
        }
        am_a[tid] = sa * (1.f / EMB);
        am_b[tid] = sb * (1.f / EMB);
        __syncthreads();
        float ga = 0.f, gb = 0.f;
        #pragma unroll 8
        for (int l = 0; l < EMB; l++) { ga += am_a[l]; gb += am_b[l]; }
        ga *= (1.f / EMB); gb *= (1.f / EMB);

        float amk = am_a[tid], bmk = am_b[tid];
        float pab = 0.f, paa = 0.f, pbb = 0.f;
        #pragma unroll 8
        for (int l = 0; l < EMB; l++) {
            float da = tik - ti[l];
            float db = tjk - tj[l];
            float A = sqrtf(da * da + 1e-8f) - amk - am_a[l] + ga;
            float B = sqrtf(db * db + 1e-8f) - bmk - am_b[l] + gb;
            pab += A * B; paa += A * A; pbb += B * B;
        }
        float SAB = block_sum_128(pab, redbuf);
        float SAA = block_sum_128(paa, redbuf);
        float SBB = block_sum_128(pbb, redbuf);
        if (tid == 0) {
            const float d2 = (float)EMB * (float)EMB;
            float dAB = sqrtf(fmaxf(SAB / d2, 0.f) + 1e-8f);
            float dAA = sqrtf(fmaxf(SAA / d2, 0.f) + 1e-8f);
            float dBB = sqrtf(fmaxf(SBB / d2, 0.f) + 1e-8f);
            atomicAdd(out_cor, dAB / sqrtf(dAA * dBB + 1e-8f));
        }
    }
}

// ---------------- gather cores (8-wide unroll for MLP) ----------------
__device__ __forceinline__ float4 gather_entity(const float* __restrict__ e_src,
                                                const float* __restrict__ r_emb,
                                                int beg, int end, unsigned lane) {
    float4 acc = make_float4(0.f, 0.f, 0.f, 0.f);
    int k = beg;
    #pragma unroll 1
    for (; k + 8 <= end; k += 8) {
        int p[8];
        #pragma unroll
        for (int t = 0; t < 8; t++) p[t] = g_epay[k + t];
        float4 e[8];
        #pragma unroll
        for (int t = 0; t < 8; t++)
            e[t] = ((const float4*)(e_src + (size_t)(p[t] >> 5) * EMB))[lane];
        #pragma unroll
        for (int t = 0; t < 8; t++) {
            float4 rv = ((const float4*)(r_emb + (size_t)(p[t] & 31) * EMB))[lane];
            fma4(acc, e[t], rv);
        }
    }
    #pragma unroll 1
    for (; k + 4 <= end; k += 4) {
        int p0 = g_epay[k], p1 = g_epay[k+1], p2 = g_epay[k+2], p3 = g_epay[k+3];
        float4 e0 = ((const float4*)(e_src + (size_t)(p0 >> 5) * EMB))[lane];
        float4 e1 = ((const float4*)(e_src + (size_t)(p1 >> 5) * EMB))[lane];
        float4 e2 = ((const float4*)(e_src + (size_t)(p2 >> 5) * EMB))[lane];
        float4 e3 = ((const float4*)(e_src + (size_t)(p3 >> 5) * EMB))[lane];
        float4 r0 = ((const float4*)(r_emb + (size_t)(p0 & 31) * EMB))[lane];
        float4 r1 = ((const float4*)(r_emb + (size_t)(p1 & 31) * EMB))[lane];
        float4 r2 = ((const float4*)(r_emb + (size_t)(p2 & 31) * EMB))[lane];
        float4 r3 = ((const float4*)(r_emb + (size_t)(p3 & 31) * EMB))[lane];
        fma4(acc, e0, r0); fma4(acc, e1, r1); fma4(acc, e2, r2); fma4(acc, e3, r3);
    }
    #pragma unroll 1
    for (; k < end; k++) {
        int p = g_epay[k];
        float4 ev = ((const float4*)(e_src + (size_t)(p >> 5) * EMB))[lane];
        float4 rv = ((const float4*)(r_emb + (size_t)(p & 31) * EMB))[lane];
        fma4(acc, ev, rv);
    }
    return acc;
}

__device__ __forceinline__ float4 gather_user(const float* __restrict__ e_src,
                                              int beg, int end, unsigned lane) {
    float4 acc = make_float4(0.f, 0.f, 0.f, 0.f);
    int k = beg;
    #pragma unroll 1
    for (; k + 8 <= end; k += 8) {
        int c[8]; float v[8];
        #pragma unroll
        for (int t = 0; t < 8; t++) { c[t] = g_icol[k + t]; v[t] = g_ival[k + t]; }
        float4 e[8];
        #pragma unroll
        for (int t = 0; t < 8; t++)
            e[t] = ((const float4*)(e_src + (size_t)c[t] * EMB))[lane];
        #pragma unroll
        for (int t = 0; t < 8; t++) fma4s(acc, e[t], v[t]);
    }
    #pragma unroll 1
    for (; k + 4 <= end; k += 4) {
        int c0 = g_icol[k], c1 = g_icol[k+1], c2 = g_icol[k+2], c3 = g_icol[k+3];
        float v0 = g_ival[k], v1 = g_ival[k+1], v2 = g_ival[k+2], v3 = g_ival[k+3];
        float4 e0 = ((const float4*)(e_src + (size_t)c0 * EMB))[lane];
        float4 e1 = ((const float4*)(e_src + (size_t)c1 * EMB))[lane];
        float4 e2 = ((const float4*)(e_src + (size_t)c2 * EMB))[lane];
        float4 e3 = ((const float4*)(e_src + (size_t)c3 * EMB))[lane];
        fma4s(acc, e0, v0); fma4s(acc, e1, v1); fma4s(acc, e2, v2); fma4s(acc, e3, v3);
    }
    #pragma unroll 1
    for (; k < end; k++) {
        float4 ev = ((const float4*)(e_src + (size_t)g_icol[k] * EMB))[lane];
        fma4s(acc, ev, g_ival[k]);
    }
    return acc;
}

__device__ __forceinline__ float4 user_epilogue(float4 acc, float4 uv, unsigned lane) {
    float4 t2[N_INT];
    float dots[N_INT];
    #pragma unroll
    for (int i = 0; i < N_INT; i++) {
        t2[i] = ((const float4*)(g_intent2 + i * EMB))[lane];
        float p = uv.x * t2[i].x + uv.y * t2[i].y + uv.z * t2[i].z + uv.w * t2[i].w;
        dots[i] = warp_sum(p);
    }
    float mx = dots[0];
    #pragma unroll
    for (int i = 1; i < N_INT; i++) mx = fmaxf(mx, dots[i]);
    float se = 0.f;
    #pragma unroll
    for (int i = 0; i < N_INT; i++) { dots[i] = expf(dots[i] - mx); se += dots[i]; }
    float inv = 1.f / se;
    float4 w = make_float4(0.f, 0.f, 0.f, 0.f);
    #pragma unroll
    for (int i = 0; i < N_INT; i++) {
        float sc = dots[i] * inv;
        fma4s(w, t2[i], sc);
    }
    float4 o = make_float4(acc.x * (1.f + w.x), acc.y * (1.f + w.y),
                           acc.z * (1.f + w.z), acc.w * (1.f + w.w));
    float ss = warp_sum(o.x * o.x + o.y * o.y + o.z * o.z + o.w * o.w);
    float in2 = 1.f / fmaxf(sqrtf(ss), 1e-12f);
    return make_float4(o.x * in2, o.y * in2, o.z * in2, o.w * in2);
}

__device__ __forceinline__ float4 l2norm4(float4 v) {
    float ss = warp_sum(v.x * v.x + v.y * v.y + v.z * v.z + v.w * v.w);
    float in2 = 1.f / fmaxf(sqrtf(ss), 1e-12f);
    return make_float4(v.x * in2, v.y * in2, v.z * in2, v.w * in2);
}

// ---------------- hop 0 split kernels ----------------
__global__ void hop0e_kernel(const float* __restrict__ entity_emb,
                             const float* __restrict__ r_emb) {
    unsigned gid = blockIdx.x * blockDim.x + threadIdx.x;
    unsigned row = gid >> 5, lane = gid & 31;
    if (row >= N_ENT) return;
    int beg = g_ecnt[row], end = g_ecnt[row + 1];
    float4 acc = gather_entity(entity_emb, r_emb, beg, end, lane);
    int cnt = end - beg;
    float inv = (cnt > 0) ? (1.f / (float)cnt) : 0.f;
    float4 v = make_float4(acc.x * inv, acc.y * inv, acc.z * inv, acc.w * inv);
    ((float4*)(g_e1 + (size_t)row * EMB))[lane] = l2norm4(v);
}

__global__ void hop0u_kernel(const float* __restrict__ entity_emb,
                             const float* __restrict__ user_emb) {
    unsigned gid = blockIdx.x * blockDim.x + threadIdx.x;
    unsigned ur = gid >> 5, lane = gid & 31;
    if (ur >= N_USERS) return;
    float4 uv = ((const float4*)(user_emb + (size_t)ur * EMB))[lane];
    int beg = g_ucnt[ur], end = g_ucnt[ur + 1];
    float4 acc = gather_user(entity_emb, beg, end, lane);
    ((float4*)(g_u1 + (size_t)ur * EMB))[lane] = user_epilogue(acc, uv, lane);
}

// ---------------- hop 1: (g_e1, g_u1) -> residuals in d_out ----------------
__global__ void hop1_kernel(const float* __restrict__ entity_emb,
                            const float* __restrict__ user_emb,
                            const float* __restrict__ r_emb,
                            float* __restrict__ res_e,
                            float* __restrict__ res_u) {
    unsigned gid = blockIdx.x * blockDim.x + threadIdx.x;
    unsigned row = gid >> 5, lane = gid & 31;
    if (row < N_ENT) {
        int beg = g_ecnt[row], end = g_ecnt[row + 1];
        float4 acc = gather_entity(g_e1, r_emb, beg, end, lane);
        int cnt = end - beg;
        float inv = (cnt > 0) ? (1.f / (float)cnt) : 0.f;
        float4 v = make_float4(acc.x * inv, acc.y * inv, acc.z * inv, acc.w * inv);
        float4 vn = l2norm4(v);
        float4 e0 = ((const float4*)(entity_emb + (size_t)row * EMB))[lane];
        float4 e1 = ((const float4*)(g_e1 + (size_t)row * EMB))[lane];
        ((float4*)(res_e + (size_t)row * EMB))[lane] =
            make_float4(e0.x + e1.x + vn.x, e0.y + e1.y + vn.y,
                        e0.z + e1.z + vn.z, e0.w + e1.w + vn.w);
    } else if (row < N_ENT + N_USERS) {
        unsigned ur = row - N_ENT;
        float4 uv = ((const float4*)(g_u1 + (size_t)ur * EMB))[lane];
        int beg = g_ucnt[ur], end = g_ucnt[ur + 1];
        float4 acc = gather_user(g_e1, beg, end, lane);
        float4 on = user_epilogue(acc, uv, lane);
        float4 u0 = ((const float4*)(user_emb + (size_t)ur * EMB))[lane];
        ((float4*)(res_u + (size_t)ur * EMB))[lane] =
            make_float4(u0.x + uv.x + on.x, u0.y + uv.y + on.y,
                        u0.z + uv.z + on.z, u0.w + uv.w + on.w);
    }
}

// ---------------- launch ----------------
extern "C" void kernel_launch(void* const* d_in, const int* in_sizes, int n_in,
                              void* d_out, int out_size) {
    const float* user_emb   = (const float*)d_in[0];
    const float* entity_emb = (const float*)d_in[1];
    const float* intent_emb = (const float*)d_in[2];
    const int*   edge_index = (const int*)d_in[3];
    const int*   edge_type  = (const int*)d_in[4];
    const int*   irows      = (const int*)d_in[5];
    const int*   icols      = (const int*)d_in[6];
    const float* ivals      = (const float*)d_in[7];
    const float* r_emb      = (const float*)d_in[8];

    float* out   = (float*)d_out;
    float* res_e = out;
    float* res_u = out + (size_t)N_ENT * EMB;
    float* cor_o = out + (size_t)N_ENT * EMB + (size_t)N_USERS * EMB;

    static cudaStream_t s2 = nullptr;
    static cudaEvent_t ev_fork = nullptr, ev_join = nullptr;
    if (!s2) {
        cudaStreamCreate(&s2);
        cudaEventCreateWithFlags(&ev_fork, cudaEventDisableTiming);
        cudaEventCreateWithFlags(&ev_join, cudaEventDisableTiming);
    }

    void* p_ecnt = nullptr; void* p_ucnt = nullptr;
    cudaGetSymbolAddress(&p_ecnt, g_ecnt);
    cudaGetSymbolAddress(&p_ucnt, g_ucnt);

    // fork side stream s2: intent/cor + user-side CSR + hop0u
    cudaEventRecord(ev_fork, 0);
    cudaStreamWaitEvent(s2, ev_fork, 0);
    cudaMemsetAsync(cor_o, 0, sizeof(float), s2);
    cudaMemsetAsync(p_ucnt, 0, sizeof(int) * (N_USERS + 1), s2);
    intent_cor_kernel<<<11, 128, 0, s2>>>(intent_emb, r_emb, cor_o);
    count_u_kernel<<<(NNZ + 255) / 256, 256, 0, s2>>>(irows);
    {
        int* cnt = (int*)p_ucnt;
        int* cur = nullptr; cudaGetSymbolAddress((void**)&cur, g_ucur);
        scan_side_kernel<<<1, 1024, 0, s2>>>(cnt, cur, N_USERS);
    }
    fill_u_kernel<<<(NNZ + 255) / 256, 256, 0, s2>>>(irows, icols, ivals);
    hop0u_kernel<<<(int)(((size_t)N_USERS * 32 + 255) / 256), 256, 0, s2>>>(entity_emb, user_emb);
    cudaEventRecord(ev_join, s2);

    // main stream: entity-side CSR + hop0e
    cudaMemsetAsync(p_ecnt, 0, sizeof(int) * (N_ENT + 1));
    count_e_kernel<<<(N_EDGES + 255) / 256, 256>>>(edge_index);
    {
        int* cnt = (int*)p_ecnt;
        int* cur = nullptr; cudaGetSymbolAddress((void**)&cur, g_ecur);
        scan_side_kernel<<<1, 1024>>>(cnt, cur, N_ENT);
    }
    fill_e_kernel<<<(N_EDGES + 255) / 256, 256>>>(edge_index, edge_type);
    hop0e_kernel<<<(int)(((size_t)N_ENT * 32 + 255) / 256), 256>>>(entity_emb, r_emb);

    // join: hop1 needs g_e1 (s1) + g_u1, g_intent2 (s2)
    cudaStreamWaitEvent(0, ev_join, 0);

    const int fin_total = N_ENT + N_USERS;
    const int hop_blocks = (int)(((size_t)fin_total * 32 + 255) / 256);
    hop1_kernel<<<hop_blocks, 256>>>(entity_emb, user_emb, r_emb, res_e, res_u);

    (void)in_sizes; (void)n_in; (void)out_size;
}

// round 7
// speedup vs baseline: 3.3351x; 1.4194x over previous
#include <cuda_runtime.h>
#include <math.h>

#define N_USERS 50000
#define N_ENT   100000
#define N_INT   5
#define EMB     128
#define N_REL   20
#define N_EDGES 1000000
#define NNZ     1000000
#define E_STRIDE 64
#define U_STRIDE 64

// ---------------- scratch (device globals; no runtime allocation) ----------------
__device__ __align__(16) float g_e1[(size_t)N_ENT * EMB];     // hop-0 entity output
__device__ __align__(16) float g_u1[(size_t)N_USERS * EMB];   // hop-0 user output
__device__ __align__(16) float g_intent2[N_INT * EMB];

__device__ int  g_ecur[N_ENT];                     // fill cursors == final counts
__device__ int  g_ucur[N_USERS];
__device__ int  g_epay[(size_t)N_ENT * E_STRIDE];  // ELL: tail*32 + rel
__device__ int2 g_ipay[(size_t)N_USERS * U_STRIDE];// ELL: (col, val bits)

// ---------------- helpers ----------------
__device__ __forceinline__ float warp_sum(float v) {
    #pragma unroll
    for (int o = 16; o; o >>= 1) v += __shfl_xor_sync(0xffffffffu, v, o);
    return v;
}
__device__ __forceinline__ void fma4(float4& a, float4 e, float4 r) {
    a.x += e.x * r.x; a.y += e.y * r.y; a.z += e.z * r.z; a.w += e.w * r.w;
}
__device__ __forceinline__ void fma4s(float4& a, float4 e, float s) {
    a.x += e.x * s; a.y += e.y * s; a.z += e.z * s; a.w += e.w * s;
}

// ---------------- ELL fill (no count/scan needed) ----------------
__global__ void fill_e_kernel(const int* __restrict__ edge_index,
                              const int* __restrict__ edge_type) {
    int i = blockIdx.x * blockDim.x + threadIdx.x;
    if (i >= N_EDGES) return;
    int head = edge_index[i];
    int tail = edge_index[N_EDGES + i];
    int rel  = edge_type[i] - 1;
    int slot = atomicAdd(&g_ecur[head], 1);
    if (slot < E_STRIDE)
        g_epay[(size_t)head * E_STRIDE + slot] = (tail << 5) | rel;
}

__global__ void fill_u_kernel(const int* __restrict__ irows,
                              const int* __restrict__ icols,
                              const float* __restrict__ ivals) {
    int i = blockIdx.x * blockDim.x + threadIdx.x;
    if (i >= NNZ) return;
    int r = irows[i];
    int slot = atomicAdd(&g_ucur[r], 1);
    if (slot < U_STRIDE)
        g_ipay[(size_t)r * U_STRIDE + slot] = make_int2(icols[i], __float_as_int(ivals[i]));
}

// ---------------- merged small-work kernel: block 0 intent2, blocks 1-10 cor ------
__device__ float block_sum_128(float v, float* sh) {
    v = warp_sum(v);
    int w = threadIdx.x >> 5;
    if ((threadIdx.x & 31) == 0) sh[w] = v;
    __syncthreads();
    float r = sh[0] + sh[1] + sh[2] + sh[3];
    __syncthreads();
    return r;
}

__global__ void intent_cor_kernel(const float* __restrict__ intent_emb,
                                  const float* __restrict__ r_emb,
                                  float* __restrict__ out_cor) {
    int tid = threadIdx.x;  // 128
    int lane = tid & 31, wid = tid >> 5;

    if (blockIdx.x == 0) {
        __shared__ float r[N_REL][EMB];
        __shared__ float ie[N_INT][EMB];
        __shared__ float att[N_REL];
        for (int i = tid; i < N_REL * EMB; i += 128)
            r[i / EMB][i % EMB] = r_emb[i];
        for (int i = tid; i < N_INT * EMB; i += 128)
            ie[i / EMB][i % EMB] = intent_emb[i];
        __syncthreads();

        const int starts[5] = {0, 0, 4, 8, 12};
        const int counts[5] = {20, 4, 4, 4, 8};

        for (int i = 0; i < N_INT; i++) {
            int s = starts[i], n = counts[i];
            for (int rel = wid; rel < n; rel += 4) {
                float d = 0.f;
                #pragma unroll
                for (int t = 0; t < 4; t++)
                    d += ie[i][lane * 4 + t] * r[s + rel][lane * 4 + t];
                d = warp_sum(d);
                if (lane == 0) att[rel] = d;
            }
            __syncthreads();
            if (tid == 0) {
                float mx = -1e30f;
                for (int q = 0; q < n; q++) mx = fmaxf(mx, att[q]);
                float se = 0.f;
                for (int q = 0; q < n; q++) { att[q] = expf(att[q] - mx); se += att[q]; }
                float inv = 1.f / se;
                for (int q = 0; q < n; q++) att[q] *= inv;
            }
            __syncthreads();
            {
                float acc = 0.f;
                for (int q = 0; q < n; q++) acc += att[q] * r[s + q][tid];
                acc /= (float)n;
                g_intent2[i * EMB + tid] = 0.5f * (acc + ie[i][tid]);
            }
            __syncthreads();
        }
    } else {
        const int pi[10] = {0,0,0,0,1,1,1,2,2,3};
        const int pj[10] = {1,2,3,4,2,3,4,3,4,4};
        int i = pi[blockIdx.x - 1], j = pj[blockIdx.x - 1];

        __shared__ float ti[EMB], tj[EMB];
        __shared__ float am_a[EMB], am_b[EMB];
        __shared__ float redbuf[4];
        ti[tid] = intent_emb[i * EMB + tid];
        tj[tid] = intent_emb[j * EMB + tid];
        __syncthreads();

        float tik = ti[tid], tjk = tj[tid];
        float sa = 0.f, sb = 0.f;
        #pragma unroll 8
        for (int l = 0; l < EMB; l++) {
            float da = tik - ti[l];
            float db = tjk - tj[l];
            sa += sqrtf(da * da + 1e-8f);
            sb += sqrtf(db * db + 1e-8f);
        }
        am_a[tid] = sa * (1.f / EMB);
        am_b[tid] = sb * (1.f / EMB);
        __syncthreads();
        float ga = 0.f, gb = 0.f;
        #pragma unroll 8
        for (int l = 0; l < EMB; l++) { ga += am_a[l]; gb += am_b[l]; }
        ga *= (1.f / EMB); gb *= (1.f / EMB);

        float amk = am_a[tid], bmk = am_b[tid];
        float pab = 0.f, paa = 0.f, pbb = 0.f;
        #pragma unroll 8
        for (int l = 0; l < EMB; l++) {
            float da = tik - ti[l];
            float db = tjk - tj[l];
            float A = sqrtf(da * da + 1e-8f) - amk - am_a[l] + ga;
            float B = sqrtf(db * db + 1e-8f) - bmk - am_b[l] + gb;
            pab += A * B; paa += A * A; pbb += B * B;
        }
        float SAB = block_sum_128(pab, redbuf);
        float SAA = block_sum_128(paa, redbuf);
        float SBB = block_sum_128(pbb, redbuf);
        if (tid == 0) {
            const float d2 = (float)EMB * (float)EMB;
            float dAB = sqrtf(fmaxf(SAB / d2, 0.f) + 1e-8f);
            float dAA = sqrtf(fmaxf(SAA / d2, 0.f) + 1e-8f);
            float dBB = sqrtf(fmaxf(SBB / d2, 0.f) + 1e-8f);
            atomicAdd(out_cor, dAB / sqrtf(dAA * dBB + 1e-8f));
        }
    }
}

// ---------------- gather cores (ELL, 8-wide unroll for MLP) ----------------
__device__ __forceinline__ float4 gather_entity(const float* __restrict__ e_src,
                                                const float* __restrict__ r_emb,
                                                unsigned row, int cnt, unsigned lane) {
    const int* pay = g_epay + (size_t)row * E_STRIDE;
    float4 acc = make_float4(0.f, 0.f, 0.f, 0.f);
    int k = 0;
    #pragma unroll 1
    for (; k + 8 <= cnt; k += 8) {
        int p[8];
        #pragma unroll
        for (int t = 0; t < 8; t++) p[t] = pay[k + t];
        float4 e[8];
        #pragma unroll
        for (int t = 0; t < 8; t++)
            e[t] = ((const float4*)(e_src + (size_t)(p[t] >> 5) * EMB))[lane];
        #pragma unroll
        for (int t = 0; t < 8; t++) {
            float4 rv = ((const float4*)(r_emb + (size_t)(p[t] & 31) * EMB))[lane];
            fma4(acc, e[t], rv);
        }
    }
    #pragma unroll 1
    for (; k + 4 <= cnt; k += 4) {
        int p0 = pay[k], p1 = pay[k+1], p2 = pay[k+2], p3 = pay[k+3];
        float4 e0 = ((const float4*)(e_src + (size_t)(p0 >> 5) * EMB))[lane];
        float4 e1 = ((const float4*)(e_src + (size_t)(p1 >> 5) * EMB))[lane];
        float4 e2 = ((const float4*)(e_src + (size_t)(p2 >> 5) * EMB))[lane];
        float4 e3 = ((const float4*)(e_src + (size_t)(p3 >> 5) * EMB))[lane];
        float4 r0 = ((const float4*)(r_emb + (size_t)(p0 & 31) * EMB))[lane];
        float4 r1 = ((const float4*)(r_emb + (size_t)(p1 & 31) * EMB))[lane];
        float4 r2 = ((const float4*)(r_emb + (size_t)(p2 & 31) * EMB))[lane];
        float4 r3 = ((const float4*)(r_emb + (size_t)(p3 & 31) * EMB))[lane];
        fma4(acc, e0, r0); fma4(acc, e1, r1); fma4(acc, e2, r2); fma4(acc, e3, r3);
    }
    #pragma unroll 1
    for (; k < cnt; k++) {
        int p = pay[k];
        float4 ev = ((const float4*)(e_src + (size_t)(p >> 5) * EMB))[lane];
        float4 rv = ((const float4*)(r_emb + (size_t)(p & 31) * EMB))[lane];
        fma4(acc, ev, rv);
    }
    return acc;
}

__device__ __forceinline__ float4 gather_user(const float* __restrict__ e_src,
                                              unsigned ur, int cnt, unsigned lane) {
    const int2* pay = g_ipay + (size_t)ur * U_STRIDE;
    float4 acc = make_float4(0.f, 0.f, 0.f, 0.f);
    int k = 0;
    #pragma unroll 1
    for (; k + 8 <= cnt; k += 8) {
        int2 p[8];
        #pragma unroll
        for (int t = 0; t < 8; t++) p[t] = pay[k + t];
        float4 e[8];
        #pragma unroll
        for (int t = 0; t < 8; t++)
            e[t] = ((const float4*)(e_src + (size_t)p[t].x * EMB))[lane];
        #pragma unroll
        for (int t = 0; t < 8; t++) fma4s(acc, e[t], __int_as_float(p[t].y));
    }
    #pragma unroll 1
    for (; k + 4 <= cnt; k += 4) {
        int2 p0 = pay[k], p1 = pay[k+1], p2 = pay[k+2], p3 = pay[k+3];
        float4 e0 = ((const float4*)(e_src + (size_t)p0.x * EMB))[lane];
        float4 e1 = ((const float4*)(e_src + (size_t)p1.x * EMB))[lane];
        float4 e2 = ((const float4*)(e_src + (size_t)p2.x * EMB))[lane];
        float4 e3 = ((const float4*)(e_src + (size_t)p3.x * EMB))[lane];
        fma4s(acc, e0, __int_as_float(p0.y)); fma4s(acc, e1, __int_as_float(p1.y));
        fma4s(acc, e2, __int_as_float(p2.y)); fma4s(acc, e3, __int_as_float(p3.y));
    }
    #pragma unroll 1
    for (; k < cnt; k++) {
        int2 p = pay[k];
        float4 ev = ((const float4*)(e_src + (size_t)p.x * EMB))[lane];
        fma4s(acc, ev, __int_as_float(p.y));
    }
    return acc;
}

__device__ __forceinline__ float4 user_epilogue(float4 acc, float4 uv, unsigned lane) {
    float4 t2[N_INT];
    float dots[N_INT];
    #pragma unroll
    for (int i = 0; i < N_INT; i++) {
        t2[i] = ((const float4*)(g_intent2 + i * EMB))[lane];
        float p = uv.x * t2[i].x + uv.y * t2[i].y + uv.z * t2[i].z + uv.w * t2[i].w;
        dots[i] = warp_sum(p);
    }
    float mx = dots[0];
    #pragma unroll
    for (int i = 1; i < N_INT; i++) mx = fmaxf(mx, dots[i]);
    float se = 0.f;
    #pragma unroll
    for (int i = 0; i < N_INT; i++) { dots[i] = expf(dots[i] - mx); se += dots[i]; }
    float inv = 1.f / se;
    float4 w = make_float4(0.f, 0.f, 0.f, 0.f);
    #pragma unroll
    for (int i = 0; i < N_INT; i++) {
        float sc = dots[i] * inv;
        fma4s(w, t2[i], sc);
    }
    float4 o = make_float4(acc.x * (1.f + w.x), acc.y * (1.f + w.y),
                           acc.z * (1.f + w.z), acc.w * (1.f + w.w));
    float ss = warp_sum(o.x * o.x + o.y * o.y + o.z * o.z + o.w * o.w);
    float in2 = 1.f / fmaxf(sqrtf(ss), 1e-12f);
    return make_float4(o.x * in2, o.y * in2, o.z * in2, o.w * in2);
}

__device__ __forceinline__ float4 l2norm4(float4 v) {
    float ss = warp_sum(v.x * v.x + v.y * v.y + v.z * v.z + v.w * v.w);
    float in2 = 1.f / fmaxf(sqrtf(ss), 1e-12f);
    return make_float4(v.x * in2, v.y * in2, v.z * in2, v.w * in2);
}

// ---------------- hop kernels ----------------
__global__ void hop0e_kernel(const float* __restrict__ entity_emb,
                             const float* __restrict__ r_emb) {
    unsigned gid = blockIdx.x * blockDim.x + threadIdx.x;
    unsigned row = gid >> 5, lane = gid & 31;
    if (row >= N_ENT) return;
    int cnt = min(g_ecur[row], E_STRIDE);
    float4 acc = gather_entity(entity_emb, r_emb, row, cnt, lane);
    float inv = (cnt > 0) ? (1.f / (float)cnt) : 0.f;
    float4 v = make_float4(acc.x * inv, acc.y * inv, acc.z * inv, acc.w * inv);
    ((float4*)(g_e1 + (size_t)row * EMB))[lane] = l2norm4(v);
}

__global__ void hop0u_kernel(const float* __restrict__ entity_emb,
                             const float* __restrict__ user_emb) {
    unsigned gid = blockIdx.x * blockDim.x + threadIdx.x;
    unsigned ur = gid >> 5, lane = gid & 31;
    if (ur >= N_USERS) return;
    float4 uv = ((const float4*)(user_emb + (size_t)ur * EMB))[lane];
    int cnt = min(g_ucur[ur], U_STRIDE);
    float4 acc = gather_user(entity_emb, ur, cnt, lane);
    ((float4*)(g_u1 + (size_t)ur * EMB))[lane] = user_epilogue(acc, uv, lane);
}

__global__ void hop1e_kernel(const float* __restrict__ entity_emb,
                             const float* __restrict__ r_emb,
                             float* __restrict__ res_e) {
    unsigned gid = blockIdx.x * blockDim.x + threadIdx.x;
    unsigned row = gid >> 5, lane = gid & 31;
    if (row >= N_ENT) return;
    int cnt = min(g_ecur[row], E_STRIDE);
    float4 acc = gather_entity(g_e1, r_emb, row, cnt, lane);
    float inv = (cnt > 0) ? (1.f / (float)cnt) : 0.f;
    float4 v = make_float4(acc.x * inv, acc.y * inv, acc.z * inv, acc.w * inv);
    float4 vn = l2norm4(v);
    float4 e0 = ((const float4*)(entity_emb + (size_t)row * EMB))[lane];
    float4 e1 = ((const float4*)(g_e1 + (size_t)row * EMB))[lane];
    ((float4*)(res_e + (size_t)row * EMB))[lane] =
        make_float4(e0.x + e1.x + vn.x, e0.y + e1.y + vn.y,
                    e0.z + e1.z + vn.z, e0.w + e1.w + vn.w);
}

__global__ void hop1u_kernel(const float* __restrict__ user_emb,
                             float* __restrict__ res_u) {
    unsigned gid = blockIdx.x * blockDim.x + threadIdx.x;
    unsigned ur = gid >> 5, lane = gid & 31;
    if (ur >= N_USERS) return;
    float4 uv = ((const float4*)(g_u1 + (size_t)ur * EMB))[lane];
    int cnt = min(g_ucur[ur], U_STRIDE);
    float4 acc = gather_user(g_e1, ur, cnt, lane);
    float4 on = user_epilogue(acc, uv, lane);
    float4 u0 = ((const float4*)(user_emb + (size_t)ur * EMB))[lane];
    ((float4*)(res_u + (size_t)ur * EMB))[lane] =
        make_float4(u0.x + uv.x + on.x, u0.y + uv.y + on.y,
                    u0.z + uv.z + on.z, u0.w + uv.w + on.w);
}

// ---------------- launch ----------------
extern "C" void kernel_launch(void* const* d_in, const int* in_sizes, int n_in,
                              void* d_out, int out_size) {
    const float* user_emb   = (const float*)d_in[0];
    const float* entity_emb = (const float*)d_in[1];
    const float* intent_emb = (const float*)d_in[2];
    const int*   edge_index = (const int*)d_in[3];
    const int*   edge_type  = (const int*)d_in[4];
    const int*   irows      = (const int*)d_in[5];
    const int*   icols      = (const int*)d_in[6];
    const float* ivals      = (const float*)d_in[7];
    const float* r_emb      = (const float*)d_in[8];

    float* out   = (float*)d_out;
    float* res_e = out;
    float* res_u = out + (size_t)N_ENT * EMB;
    float* cor_o = out + (size_t)N_ENT * EMB + (size_t)N_USERS * EMB;

    static cudaStream_t s2 = nullptr;
    static cudaEvent_t ev_fork = nullptr, ev_e = nullptr, ev_join = nullptr;
    if (!s2) {
        cudaStreamCreate(&s2);
        cudaEventCreateWithFlags(&ev_fork, cudaEventDisableTiming);
        cudaEventCreateWithFlags(&ev_e, cudaEventDisableTiming);
        cudaEventCreateWithFlags(&ev_join, cudaEventDisableTiming);
    }

    void* p_ecur = nullptr; void* p_ucur = nullptr;
    cudaGetSymbolAddress(&p_ecur, g_ecur);
    cudaGetSymbolAddress(&p_ucur, g_ucur);

    // fork s2: intent/cor + user ELL + hop0u
    cudaEventRecord(ev_fork, 0);
    cudaStreamWaitEvent(s2, ev_fork, 0);
    cudaMemsetAsync(cor_o, 0, sizeof(float), s2);
    cudaMemsetAsync(p_ucur, 0, sizeof(int) * N_USERS, s2);
    intent_cor_kernel<<<11, 128, 0, s2>>>(intent_emb, r_emb, cor_o);
    fill_u_kernel<<<(NNZ + 255) / 256, 256, 0, s2>>>(irows, icols, ivals);
    hop0u_kernel<<<(int)(((size_t)N_USERS * 32 + 255) / 256), 256, 0, s2>>>(entity_emb, user_emb);

    // main: entity ELL + hop0e
    cudaMemsetAsync(p_ecur, 0, sizeof(int) * N_ENT);
    fill_e_kernel<<<(N_EDGES + 255) / 256, 256>>>(edge_index, edge_type);
    hop0e_kernel<<<(int)(((size_t)N_ENT * 32 + 255) / 256), 256>>>(entity_emb, r_emb);
    cudaEventRecord(ev_e, 0);

    // s2: hop1u needs g_u1 (s2) + g_e1 (ev_e)
    cudaStreamWaitEvent(s2, ev_e, 0);
    hop1u_kernel<<<(int)(((size_t)N_USERS * 32 + 255) / 256), 256, 0, s2>>>(user_emb, res_u);
    cudaEventRecord(ev_join, s2);

    // main: hop1e (needs only g_e1 + entity ELL)
    hop1e_kernel<<<(int)(((size_t)N_ENT * 32 + 255) / 256), 256>>>(entity_emb, r_emb, res_e);

    // final join
    cudaStreamWaitEvent(0, ev_join, 0);

    (void)in_sizes; (void)n_in; (void)out_size;
}

// round 8
// speedup vs baseline: 3.7337x; 1.1195x over previous
#include <cuda_runtime.h>
#include <cuda_fp16.h>
#include <math.h>

#define N_USERS 50000
#define N_ENT   100000
#define N_INT   5
#define EMB     128
#define N_REL   20
#define N_EDGES 1000000
#define NNZ     1000000
#define E_STRIDE 64
#define U_STRIDE 64

// ---------------- scratch (device globals; no runtime allocation) ----------------
__device__ __align__(16) float  g_e1[(size_t)N_ENT * EMB];    // hop-0 entity out (fp32)
__device__ __align__(16) __half g_e0h[(size_t)N_ENT * EMB];   // fp16 copy of entity_emb
__device__ __align__(16) __half g_e1h[(size_t)N_ENT * EMB];   // fp16 copy of g_e1
__device__ __align__(16) float  g_u1[(size_t)N_USERS * EMB];  // hop-0 user out
__device__ __align__(16) float  g_intent2[N_INT * EMB];

__device__ int  g_ecur[N_ENT];                      // fill cursors == counts
__device__ int  g_ucur[N_USERS];
__device__ int  g_epay[(size_t)N_ENT * E_STRIDE];   // ELL: tail*32 + rel
__device__ int2 g_ipay[(size_t)N_USERS * U_STRIDE]; // ELL: (col, val bits)

// ---------------- helpers ----------------
__device__ __forceinline__ float warp_sum(float v) {
    #pragma unroll
    for (int o = 16; o; o >>= 1) v += __shfl_xor_sync(0xffffffffu, v, o);
    return v;
}
__device__ __forceinline__ void fma4(float4& a, float4 e, float4 r) {
    a.x += e.x * r.x; a.y += e.y * r.y; a.z += e.z * r.z; a.w += e.w * r.w;
}
__device__ __forceinline__ void fma4s(float4& a, float4 e, float s) {
    a.x += e.x * s; a.y += e.y * s; a.z += e.z * s; a.w += e.w * s;
}
// load 4 consecutive fp16 elements (this lane's slice of a 128-elem row)
__device__ __forceinline__ float4 ld_h4(const __half* row, unsigned lane) {
    uint2 raw = ((const uint2*)row)[lane];
    __half2 h0 = *(__half2*)&raw.x, h1 = *(__half2*)&raw.y;
    float2 f0 = __half22float2(h0), f1 = __half22float2(h1);
    return make_float4(f0.x, f0.y, f1.x, f1.y);
}
__device__ __forceinline__ uint2 pack_h4(float4 v) {
    __half2 a = __floats2half2_rn(v.x, v.y);
    __half2 b = __floats2half2_rn(v.z, v.w);
    uint2 raw;
    raw.x = *(unsigned*)&a; raw.y = *(unsigned*)&b;
    return raw;
}

// ---------------- fp32 -> fp16 conversion of entity_emb ----------------
__global__ void convert_e0_kernel(const float* __restrict__ src) {
    size_t i = (size_t)blockIdx.x * blockDim.x + threadIdx.x;
    if (i >= (size_t)N_ENT * EMB / 4) return;
    float4 v = ((const float4*)src)[i];
    ((uint2*)g_e0h)[i] = pack_h4(v);
}

// ---------------- ELL fill ----------------
__global__ void fill_e_kernel(const int* __restrict__ edge_index,
                              const int* __restrict__ edge_type) {
    int i = blockIdx.x * blockDim.x + threadIdx.x;
    if (i >= N_EDGES) return;
    int head = edge_index[i];
    int tail = edge_index[N_EDGES + i];
    int rel  = edge_type[i] - 1;
    int slot = atomicAdd(&g_ecur[head], 1);
    if (slot < E_STRIDE)
        g_epay[(size_t)head * E_STRIDE + slot] = (tail << 5) | rel;
}

__global__ void fill_u_kernel(const int* __restrict__ irows,
                              const int* __restrict__ icols,
                              const float* __restrict__ ivals) {
    int i = blockIdx.x * blockDim.x + threadIdx.x;
    if (i >= NNZ) return;
    int r = irows[i];
    int slot = atomicAdd(&g_ucur[r], 1);
    if (slot < U_STRIDE)
        g_ipay[(size_t)r * U_STRIDE + slot] = make_int2(icols[i], __float_as_int(ivals[i]));
}

// ---------------- merged small-work kernel: block 0 intent2, blocks 1-10 cor ------
__device__ float block_sum_128(float v, float* sh) {
    v = warp_sum(v);
    int w = threadIdx.x >> 5;
    if ((threadIdx.x & 31) == 0) sh[w] = v;
    __syncthreads();
    float r = sh[0] + sh[1] + sh[2] + sh[3];
    __syncthreads();
    return r;
}

__global__ void intent_cor_kernel(const float* __restrict__ intent_emb,
                                  const float* __restrict__ r_emb,
                                  float* __restrict__ out_cor) {
    int tid = threadIdx.x;  // 128
    int lane = tid & 31, wid = tid >> 5;

    if (blockIdx.x == 0) {
        __shared__ float r[N_REL][EMB];
        __shared__ float ie[N_INT][EMB];
        __shared__ float att[N_REL];
        for (int i = tid; i < N_REL * EMB; i += 128)
            r[i / EMB][i % EMB] = r_emb[i];
        for (int i = tid; i < N_INT * EMB; i += 128)
            ie[i / EMB][i % EMB] = intent_emb[i];
        __syncthreads();

        const int starts[5] = {0, 0, 4, 8, 12};
        const int counts[5] = {20, 4, 4, 4, 8};

        for (int i = 0; i < N_INT; i++) {
            int s = starts[i], n = counts[i];
            for (int rel = wid; rel < n; rel += 4) {
                float d = 0.f;
                #pragma unroll
                for (int t = 0; t < 4; t++)
                    d += ie[i][lane * 4 + t] * r[s + rel][lane * 4 + t];
                d = warp_sum(d);
                if (lane == 0) att[rel] = d;
            }
            __syncthreads();
            if (tid == 0) {
                float mx = -1e30f;
                for (int q = 0; q < n; q++) mx = fmaxf(mx, att[q]);
                float se = 0.f;
                for (int q = 0; q < n; q++) { att[q] = expf(att[q] - mx); se += att[q]; }
                float inv = 1.f / se;
                for (int q = 0; q < n; q++) att[q] *= inv;
            }
            __syncthreads();
            {
                float acc = 0.f;
                for (int q = 0; q < n; q++) acc += att[q] * r[s + q][tid];
                acc /= (float)n;
                g_intent2[i * EMB + tid] = 0.5f * (acc + ie[i][tid]);
            }
            __syncthreads();
        }
    } else {
        const int pi[10] = {0,0,0,0,1,1,1,2,2,3};
        const int pj[10] = {1,2,3,4,2,3,4,3,4,4};
        int i = pi[blockIdx.x - 1], j = pj[blockIdx.x - 1];

        __shared__ float ti[EMB], tj[EMB];
        __shared__ float am_a[EMB], am_b[EMB];
        __shared__ float redbuf[4];
        ti[tid] = intent_emb[i * EMB + tid];
        tj[tid] = intent_emb[j * EMB + tid];
        __syncthreads();

        float tik = ti[tid], tjk = tj[tid];
        float sa = 0.f, sb = 0.f;
        #pragma unroll 8
        for (int l = 0; l < EMB; l++) {
            float da = tik - ti[l];
            float db = tjk - tj[l];
            sa += sqrtf(da * da + 1e-8f);
            sb += sqrtf(db * db + 1e-8f);
        }
        am_a[tid] = sa * (1.f / EMB);
        am_b[tid] = sb * (1.f / EMB);
        __syncthreads();
        float ga = 0.f, gb = 0.f;
        #pragma unroll 8
        for (int l = 0; l < EMB; l++) { ga += am_a[l]; gb += am_b[l]; }
        ga *= (1.f / EMB); gb *= (1.f / EMB);

        float amk = am_a[tid], bmk = am_b[tid];
        float pab = 0.f, paa = 0.f, pbb = 0.f;
        #pragma unroll 8
        for (int l = 0; l < EMB; l++) {
            float da = tik - ti[l];
            float db = tjk - tj[l];
            float A = sqrtf(da * da + 1e-8f) - amk - am_a[l] + ga;
            float B = sqrtf(db * db + 1e-8f) - bmk - am_b[l] + gb;
            pab += A * B; paa += A * A; pbb += B * B;
        }
        float SAB = block_sum_128(pab, redbuf);
        float SAA = block_sum_128(paa, redbuf);
        float SBB = block_sum_128(pbb, redbuf);
        if (tid == 0) {
            const float d2 = (float)EMB * (float)EMB;
            float dAB = sqrtf(fmaxf(SAB / d2, 0.f) + 1e-8f);
            float dAA = sqrtf(fmaxf(SAA / d2, 0.f) + 1e-8f);
            float dBB = sqrtf(fmaxf(SBB / d2, 0.f) + 1e-8f);
            atomicAdd(out_cor, dAB / sqrtf(dAA * dBB + 1e-8f));
        }
    }
}

// ---------------- gather cores (fp16 source, ELL, 8-wide unroll) ----------------
__device__ __forceinline__ float4 gather_entity(const __half* __restrict__ e_src,
                                                const float* __restrict__ r_emb,
                                                unsigned row, int cnt, unsigned lane) {
    const int* pay = g_epay + (size_t)row * E_STRIDE;
    float4 acc = make_float4(0.f, 0.f, 0.f, 0.f);
    int k = 0;
    #pragma unroll 1
    for (; k + 8 <= cnt; k += 8) {
        int p[8];
        #pragma unroll
        for (int t = 0; t < 8; t++) p[t] = pay[k + t];
        float4 e[8];
        #pragma unroll
        for (int t = 0; t < 8; t++)
            e[t] = ld_h4(e_src + (size_t)(p[t] >> 5) * EMB, lane);
        #pragma unroll
        for (int t = 0; t < 8; t++) {
            float4 rv = ((const float4*)(r_emb + (size_t)(p[t] & 31) * EMB))[lane];
            fma4(acc, e[t], rv);
        }
    }
    #pragma unroll 1
    for (; k + 4 <= cnt; k += 4) {
        int p0 = pay[k], p1 = pay[k+1], p2 = pay[k+2], p3 = pay[k+3];
        float4 e0 = ld_h4(e_src + (size_t)(p0 >> 5) * EMB, lane);
        float4 e1 = ld_h4(e_src + (size_t)(p1 >> 5) * EMB, lane);
        float4 e2 = ld_h4(e_src + (size_t)(p2 >> 5) * EMB, lane);
        float4 e3 = ld_h4(e_src + (size_t)(p3 >> 5) * EMB, lane);
        float4 r0 = ((const float4*)(r_emb + (size_t)(p0 & 31) * EMB))[lane];
        float4 r1 = ((const float4*)(r_emb + (size_t)(p1 & 31) * EMB))[lane];
        float4 r2 = ((const float4*)(r_emb + (size_t)(p2 & 31) * EMB))[lane];
        float4 r3 = ((const float4*)(r_emb + (size_t)(p3 & 31) * EMB))[lane];
        fma4(acc, e0, r0); fma4(acc, e1, r1); fma4(acc, e2, r2); fma4(acc, e3, r3);
    }
    #pragma unroll 1
    for (; k < cnt; k++) {
        int p = pay[k];
        float4 ev = ld_h4(e_src + (size_t)(p >> 5) * EMB, lane);
        float4 rv = ((const float4*)(r_emb + (size_t)(p & 31) * EMB))[lane];
        fma4(acc, ev, rv);
    }
    return acc;
}

__device__ __forceinline__ float4 gather_user(const __half* __restrict__ e_src,
                                              unsigned ur, int cnt, unsigned lane) {
    const int2* pay = g_ipay + (size_t)ur * U_STRIDE;
    float4 acc = make_float4(0.f, 0.f, 0.f, 0.f);
    int k = 0;
    #pragma unroll 1
    for (; k + 8 <= cnt; k += 8) {
        int2 p[8];
        #pragma unroll
        for (int t = 0; t < 8; t++) p[t] = pay[k + t];
        float4 e[8];
        #pragma unroll
        for (int t = 0; t < 8; t++)
            e[t] = ld_h4(e_src + (size_t)p[t].x * EMB, lane);
        #pragma unroll
        for (int t = 0; t < 8; t++) fma4s(acc, e[t], __int_as_float(p[t].y));
    }
    #pragma unroll 1
    for (; k + 4 <= cnt; k += 4) {
        int2 p0 = pay[k], p1 = pay[k+1], p2 = pay[k+2], p3 = pay[k+3];
        float4 e0 = ld_h4(e_src + (size_t)p0.x * EMB, lane);
        float4 e1 = ld_h4(e_src + (size_t)p1.x * EMB, lane);
        float4 e2 = ld_h4(e_src + (size_t)p2.x * EMB, lane);
        float4 e3 = ld_h4(e_src + (size_t)p3.x * EMB, lane);
        fma4s(acc, e0, __int_as_float(p0.y)); fma4s(acc, e1, __int_as_float(p1.y));
        fma4s(acc, e2, __int_as_float(p2.y)); fma4s(acc, e3, __int_as_float(p3.y));
    }
    #pragma unroll 1
    for (; k < cnt; k++) {
        int2 p = pay[k];
        float4 ev = ld_h4(e_src + (size_t)p.x * EMB, lane);
        fma4s(acc, ev, __int_as_float(p.y));
    }
    return acc;
}

__device__ __forceinline__ float4 user_epilogue(float4 acc, float4 uv, unsigned lane) {
    float4 t2[N_INT];
    float dots[N_INT];
    #pragma unroll
    for (int i = 0; i < N_INT; i++) {
        t2[i] = ((const float4*)(g_intent2 + i * EMB))[lane];
        float p = uv.x * t2[i].x + uv.y * t2[i].y + uv.z * t2[i].z + uv.w * t2[i].w;
        dots[i] = warp_sum(p);
    }
    float mx = dots[0];
    #pragma unroll
    for (int i = 1; i < N_INT; i++) mx = fmaxf(mx, dots[i]);
    float se = 0.f;
    #pragma unroll
    for (int i = 0; i < N_INT; i++) { dots[i] = expf(dots[i] - mx); se += dots[i]; }
    float inv = 1.f / se;
    float4 w = make_float4(0.f, 0.f, 0.f, 0.f);
    #pragma unroll
    for (int i = 0; i < N_INT; i++) {
        float sc = dots[i] * inv;
        fma4s(w, t2[i], sc);
    }
    float4 o = make_float4(acc.x * (1.f + w.x), acc.y * (1.f + w.y),
                           acc.z * (1.f + w.z), acc.w * (1.f + w.w));
    float ss = warp_sum(o.x * o.x + o.y * o.y + o.z * o.z + o.w * o.w);
    float in2 = 1.f / fmaxf(sqrtf(ss), 1e-12f);
    return make_float4(o.x * in2, o.y * in2, o.z * in2, o.w * in2);
}

__device__ __forceinline__ float4 l2norm4(float4 v) {
    float ss = warp_sum(v.x * v.x + v.y * v.y + v.z * v.z + v.w * v.w);
    float in2 = 1.f / fmaxf(sqrtf(ss), 1e-12f);
    return make_float4(v.x * in2, v.y * in2, v.z * in2, v.w * in2);
}

// ---------------- hop kernels ----------------
__global__ void hop0e_kernel(const float* __restrict__ r_emb) {
    unsigned gid = blockIdx.x * blockDim.x + threadIdx.x;
    unsigned row = gid >> 5, lane = gid & 31;
    if (row >= N_ENT) return;
    int cnt = min(g_ecur[row], E_STRIDE);
    float4 acc = gather_entity(g_e0h, r_emb, row, cnt, lane);
    float inv = (cnt > 0) ? (1.f / (float)cnt) : 0.f;
    float4 v = make_float4(acc.x * inv, acc.y * inv, acc.z * inv, acc.w * inv);
    float4 vn = l2norm4(v);
    ((float4*)(g_e1 + (size_t)row * EMB))[lane] = vn;
    ((uint2*)(g_e1h + (size_t)row * EMB))[lane] = pack_h4(vn);
}

__global__ void hop0u_kernel(const float* __restrict__ user_emb) {
    unsigned gid = blockIdx.x * blockDim.x + threadIdx.x;
    unsigned ur = gid >> 5, lane = gid & 31;
    if (ur >= N_USERS) return;
    float4 uv = ((const float4*)(user_emb + (size_t)ur * EMB))[lane];
    int cnt = min(g_ucur[ur], U_STRIDE);
    float4 acc = gather_user(g_e0h, ur, cnt, lane);
    ((float4*)(g_u1 + (size_t)ur * EMB))[lane] = user_epilogue(acc, uv, lane);
}

__global__ void hop1e_kernel(const float* __restrict__ entity_emb,
                             const float* __restrict__ r_emb,
                             float* __restrict__ res_e) {
    unsigned gid = blockIdx.x * blockDim.x + threadIdx.x;
    unsigned row = gid >> 5, lane = gid & 31;
    if (row >= N_ENT) return;
    int cnt = min(g_ecur[row], E_STRIDE);
    float4 acc = gather_entity(g_e1h, r_emb, row, cnt, lane);
    float inv = (cnt > 0) ? (1.f / (float)cnt) : 0.f;
    float4 v = make_float4(acc.x * inv, acc.y * inv, acc.z * inv, acc.w * inv);
    float4 vn = l2norm4(v);
    float4 e0 = ((const float4*)(entity_emb + (size_t)row * EMB))[lane];
    float4 e1 = ((const float4*)(g_e1 + (size_t)row * EMB))[lane];
    ((float4*)(res_e + (size_t)row * EMB))[lane] =
        make_float4(e0.x + e1.x + vn.x, e0.y + e1.y + vn.y,
                    e0.z + e1.z + vn.z, e0.w + e1.w + vn.w);
}

__global__ void hop1u_kernel(const float* __restrict__ user_emb,
                             float* __restrict__ res_u) {
    unsigned gid = blockIdx.x * blockDim.x + threadIdx.x;
    unsigned ur = gid >> 5, lane = gid & 31;
    if (ur >= N_USERS) return;
    float4 uv = ((const float4*)(g_u1 + (size_t)ur * EMB))[lane];
    int cnt = min(g_ucur[ur], U_STRIDE);
    float4 acc = gather_user(g_e1h, ur, cnt, lane);
    float4 on = user_epilogue(acc, uv, lane);
    float4 u0 = ((const float4*)(user_emb + (size_t)ur * EMB))[lane];
    ((float4*)(res_u + (size_t)ur * EMB))[lane] =
        make_float4(u0.x + uv.x + on.x, u0.y + uv.y + on.y,
                    u0.z + uv.z + on.z, u0.w + uv.w + on.w);
}

// ---------------- launch ----------------
extern "C" void kernel_launch(void* const* d_in, const int* in_sizes, int n_in,
                              void* d_out, int out_size) {
    const float* user_emb   = (const float*)d_in[0];
    const float* entity_emb = (const float*)d_in[1];
    const float* intent_emb = (const float*)d_in[2];
    const int*   edge_index = (const int*)d_in[3];
    const int*   edge_type  = (const int*)d_in[4];
    const int*   irows      = (const int*)d_in[5];
    const int*   icols      = (const int*)d_in[6];
    const float* ivals      = (const float*)d_in[7];
    const float* r_emb      = (const float*)d_in[8];

    float* out   = (float*)d_out;
    float* res_e = out;
    float* res_u = out + (size_t)N_ENT * EMB;
    float* cor_o = out + (size_t)N_ENT * EMB + (size_t)N_USERS * EMB;

    static cudaStream_t s2 = nullptr, s3 = nullptr;
    static cudaEvent_t ev_fork = nullptr, ev_cvt = nullptr, ev_e = nullptr, ev_join = nullptr;
    if (!s2) {
        cudaStreamCreate(&s2);
        cudaStreamCreate(&s3);
        cudaEventCreateWithFlags(&ev_fork, cudaEventDisableTiming);
        cudaEventCreateWithFlags(&ev_cvt, cudaEventDisableTiming);
        cudaEventCreateWithFlags(&ev_e, cudaEventDisableTiming);
        cudaEventCreateWithFlags(&ev_join, cudaEventDisableTiming);
    }

    void* p_ecur = nullptr; void* p_ucur = nullptr;
    cudaGetSymbolAddress(&p_ecur, g_ecur);
    cudaGetSymbolAddress(&p_ucur, g_ucur);

    cudaEventRecord(ev_fork, 0);
    cudaStreamWaitEvent(s2, ev_fork, 0);
    cudaStreamWaitEvent(s3, ev_fork, 0);

    // s3: fp32->fp16 convert of entity_emb (overlaps ELL fills)
    convert_e0_kernel<<<(int)(((size_t)N_ENT * EMB / 4 + 255) / 256), 256, 0, s3>>>(entity_emb);
    cudaEventRecord(ev_cvt, s3);

    // s2: intent/cor + user ELL + hop0u
    cudaMemsetAsync(cor_o, 0, sizeof(float), s2);
    cudaMemsetAsync(p_ucur, 0, sizeof(int) * N_USERS, s2);
    intent_cor_kernel<<<11, 128, 0, s2>>>(intent_emb, r_emb, cor_o);
    fill_u_kernel<<<(NNZ + 255) / 256, 256, 0, s2>>>(irows, icols, ivals);
    cudaStreamWaitEvent(s2, ev_cvt, 0);
    hop0u_kernel<<<(int)(((size_t)N_USERS * 32 + 255) / 256), 256, 0, s2>>>(user_emb);

    // main: entity ELL + hop0e
    cudaMemsetAsync(p_ecur, 0, sizeof(int) * N_ENT);
    fill_e_kernel<<<(N_EDGES + 255) / 256, 256>>>(edge_index, edge_type);
    cudaStreamWaitEvent(0, ev_cvt, 0);
    hop0e_kernel<<<(int)(((size_t)N_ENT * 32 + 255) / 256), 256>>>(r_emb);
    cudaEventRecord(ev_e, 0);

    // s2: hop1u needs g_u1 (s2) + g_e1h (ev_e)
    cudaStreamWaitEvent(s2, ev_e, 0);
    hop1u_kernel<<<(int)(((size_t)N_USERS * 32 + 255) / 256), 256, 0, s2>>>(user_emb, res_u);
    cudaEventRecord(ev_join, s2);

    // main: hop1e
    hop1e_kernel<<<(int)(((size_t)N_ENT * 32 + 255) / 256), 256>>>(entity_emb, r_emb, res_e);

    // final join
    cudaStreamWaitEvent(0, ev_join, 0);

    (void)in_sizes; (void)n_in; (void)out_size;
}